// round 2
// baseline (speedup 1.0000x reference)
#include <cuda_runtime.h>
#include <cuda_bf16.h>

#define NN   4096
#define INF  256
#define HD   256   // H*D
#define H    4
#define D    64
#define TI   16
#define TJ   64

// scratch (no cudaMalloc allowed)
__device__ float g_h  [NN * HD];
__device__ float g_si [NN * H];
__device__ float g_sj [NN * H];
__device__ float g_epi[NN * H];
__device__ float g_eni[NN * H];
__device__ float g_epj[NN * H];
__device__ float g_enj[NN * H];

// ---------------- K1: h = x @ W  (4096x256 @ 256x256) ----------------
__global__ __launch_bounds__(256) void gemm_xw(const float* __restrict__ x,
                                               const float* __restrict__ W) {
    __shared__ float As[16][65];   // [k][m], padded
    __shared__ float Bs[16][64];   // [k][n]
    const int t  = threadIdx.x;
    const int tx = t & 15, ty = t >> 4;
    const int m0 = blockIdx.y * 64;
    const int n0 = blockIdx.x * 64;

    float acc[4][4];
#pragma unroll
    for (int i = 0; i < 4; i++)
#pragma unroll
        for (int j = 0; j < 4; j++) acc[i][j] = 0.f;

    for (int k0 = 0; k0 < INF; k0 += 16) {
        {   // load x tile transposed: As[k][m]
            int m  = t >> 2;
            int kq = (t & 3) << 2;
            float4 v = *(const float4*)&x[(m0 + m) * INF + k0 + kq];
            As[kq + 0][m] = v.x; As[kq + 1][m] = v.y;
            As[kq + 2][m] = v.z; As[kq + 3][m] = v.w;
        }
#pragma unroll
        for (int r = 0; r < 4; r++) {   // load W tile: Bs[k][n]
            int k = (t >> 6) + (r << 2);
            int n = t & 63;
            Bs[k][n] = W[(k0 + k) * HD + n0 + n];
        }
        __syncthreads();
#pragma unroll
        for (int k = 0; k < 16; k++) {
            float a[4], b[4];
#pragma unroll
            for (int i = 0; i < 4; i++) a[i] = As[k][ty * 4 + i];
#pragma unroll
            for (int j = 0; j < 4; j++) b[j] = Bs[k][tx * 4 + j];
#pragma unroll
            for (int i = 0; i < 4; i++)
#pragma unroll
                for (int j = 0; j < 4; j++) acc[i][j] += a[i] * b[j];
        }
        __syncthreads();
    }
#pragma unroll
    for (int i = 0; i < 4; i++)
#pragma unroll
        for (int j = 0; j < 4; j++)
            g_h[(m0 + ty * 4 + i) * HD + n0 + tx * 4 + j] = acc[i][j];
}

// ---------------- K2: si/sj dots + exp factor precompute ----------------
__global__ __launch_bounds__(256) void scores(const float* __restrict__ a1,
                                              const float* __restrict__ a2) {
    int idx = blockIdx.x * blockDim.x + threadIdx.x;   // 0..NN*H-1
    if (idx >= NN * H) return;
    int n = idx >> 2, h = idx & 3;
    const float4* row = (const float4*)&g_h[n * HD + h * D];
    const float4* A1  = (const float4*)(a1);
    const float4* A2  = (const float4*)(a2);
    float s1 = 0.f, s2 = 0.f;
#pragma unroll
    for (int q = 0; q < D / 4; q++) {
        float4 v  = row[q];
        float4 c1 = __ldg(&A1[q]);
        float4 c2 = __ldg(&A2[q]);
        s1 += v.x * c1.x + v.y * c1.y + v.z * c1.z + v.w * c1.w;
        s2 += v.x * c2.x + v.y * c2.y + v.z * c2.z + v.w * c2.w;
    }
    g_si [idx] = s1;
    g_sj [idx] = s2;
    g_epi[idx] = __expf(s1);
    g_eni[idx] = __expf(0.2f * s1);
    g_epj[idx] = __expf(s2);
    g_enj[idx] = __expf(0.2f * s2);
}

// ---------------- K3: fused masked-softmax weights + aggregation ----------------
// block = 256 threads; block handles TI=16 destination rows, sweeps j in TJ=64 tiles.
// exp(leaky_relu(si+sj)) = (si+sj>0) ? exp(si)exp(sj) : exp(.2si)exp(.2sj)  -> no exp in loop
__global__ __launch_bounds__(256) void aggregate(const int* __restrict__ adj,
                                                 float* __restrict__ out) {
    __shared__ float si_s [TI * H], epi_s[TI * H], eni_s[TI * H];
    __shared__ float sj_s [TJ * H], epj_s[TJ * H], enj_s[TJ * H];
    __shared__ float wbuf [TJ * 68];          // row stride 68 floats (16B aligned, bank-spread)
    __shared__ float Zs   [TI * H];           // indexed (h<<4)|i

    const int t  = threadIdx.x;
    const int i0 = blockIdx.x * TI;

    // main-loop identity: one feature per thread
    const int hF = t >> 6;                    // head
    // w-phase identity: pair p=(i,h), 4 threads per pair
    const int p  = t >> 2;
    const int il = p & 15;
    const int hh = p >> 4;
    const int jj = t & 3;

    if (t < TI * H) {
        si_s [t] = g_si [i0 * H + t];
        epi_s[t] = g_epi[i0 * H + t];
        eni_s[t] = g_eni[i0 * H + t];
        Zs[t] = 0.f;
    }
    __syncthreads();

    const float siv  = si_s [il * H + hh];
    const float epiv = epi_s[il * H + hh];
    const float eniv = eni_s[il * H + hh];

    float acc[TI];
#pragma unroll
    for (int i = 0; i < TI; i++) acc[i] = 0.f;

    for (int jt = 0; jt < NN / TJ; jt++) {
        const int j0 = jt * TJ;
        __syncthreads();                       // wbuf free to overwrite
        // stage sj tile (TJ*H = 256 elements per array, fully coalesced)
        sj_s [t] = g_sj [j0 * H + t];
        epj_s[t] = g_epj[j0 * H + t];
        enj_s[t] = g_enj[j0 * H + t];
        __syncthreads();

        // ---- weight generation ----
        float zp = 0.f;
        const int* arow = adj + (long)(i0 + il) * NN + j0;
#pragma unroll
        for (int k = 0; k < 16; k++) {
            const int jl = jj + (k << 2);
            const int av = arow[jl];
            const float s = siv + sj_s[jl * H + hh];
            float w = 0.f;
            if (av > 0)
                w = (s > 0.f) ? epiv * epj_s[jl * H + hh]
                              : eniv * enj_s[jl * H + hh];
            wbuf[jl * 68 + (hh << 4) + il] = w;
            zp += w;
        }
        zp += __shfl_xor_sync(0xffffffffu, zp, 1);
        zp += __shfl_xor_sync(0xffffffffu, zp, 2);
        if (jj == 0) Zs[(hh << 4) + il] += zp;
        __syncthreads();

        // ---- aggregation: acc[i] += w[i][j][h] * h[j][f] ----
        const float* hcol = g_h + (long)j0 * HD + t;
        const float* wrow = wbuf + (hF << 4);
#pragma unroll 4
        for (int jl = 0; jl < TJ; jl++) {
            const float hv = hcol[(long)jl * HD];
            const float4* wp = (const float4*)(wrow + jl * 68);
            float4 w0 = wp[0], w1 = wp[1], w2 = wp[2], w3 = wp[3];
            acc[0]  += w0.x * hv;  acc[1]  += w0.y * hv;
            acc[2]  += w0.z * hv;  acc[3]  += w0.w * hv;
            acc[4]  += w1.x * hv;  acc[5]  += w1.y * hv;
            acc[6]  += w1.z * hv;  acc[7]  += w1.w * hv;
            acc[8]  += w2.x * hv;  acc[9]  += w2.y * hv;
            acc[10] += w2.z * hv;  acc[11] += w2.w * hv;
            acc[12] += w3.x * hv;  acc[13] += w3.y * hv;
            acc[14] += w3.z * hv;  acc[15] += w3.w * hv;
        }
    }
    __syncthreads();

    // ---- epilogue: normalize and store ----
#pragma unroll
    for (int i = 0; i < TI; i++) {
        const float z = Zs[(hF << 4) + i];
        out[(long)(i0 + i) * HD + t] = __fdividef(acc[i], z);
    }
}

extern "C" void kernel_launch(void* const* d_in, const int* in_sizes, int n_in,
                              void* d_out, int out_size) {
    const float* x   = (const float*)d_in[0];
    const int*   adj = (const int*)  d_in[1];
    const float* W   = (const float*)d_in[2];
    const float* a1  = (const float*)d_in[3];
    const float* a2  = (const float*)d_in[4];
    float* out = (float*)d_out;

    gemm_xw  <<<dim3(HD / 64, NN / 64), 256>>>(x, W);
    scores   <<<(NN * H) / 256, 256>>>(a1, a2);
    aggregate<<<NN / TI, 256>>>(adj, out);
}

// round 6
// speedup vs baseline: 1.0023x; 1.0023x over previous
#include <cuda_runtime.h>
#include <cuda_bf16.h>

#define NN   4096
#define INF  256
#define HD   256   // H*D
#define H    4
#define D    64
#define TI   16
#define TJ   64

// scratch (no cudaMalloc allowed)
__device__ float g_h  [NN * HD];
__device__ float g_si [NN * H];
__device__ float g_sj [NN * H];
__device__ float g_epi[NN * H];
__device__ float g_eni[NN * H];
__device__ float g_epj[NN * H];
__device__ float g_enj[NN * H];

// ---------------- K1: h = x @ W  (4096x256 @ 256x256) ----------------
__global__ __launch_bounds__(256) void gemm_xw(const float* __restrict__ x,
                                               const float* __restrict__ W) {
    __shared__ float As[16][65];   // [k][m], padded
    __shared__ float Bs[16][64];   // [k][n]
    const int t  = threadIdx.x;
    const int tx = t & 15, ty = t >> 4;
    const int m0 = blockIdx.y * 64;
    const int n0 = blockIdx.x * 64;

    float acc[4][4];
#pragma unroll
    for (int i = 0; i < 4; i++)
#pragma unroll
        for (int j = 0; j < 4; j++) acc[i][j] = 0.f;

    for (int k0 = 0; k0 < INF; k0 += 16) {
        {   // load x tile transposed: As[k][m]
            int m  = t >> 2;
            int kq = (t & 3) << 2;
            float4 v = *(const float4*)&x[(m0 + m) * INF + k0 + kq];
            As[kq + 0][m] = v.x; As[kq + 1][m] = v.y;
            As[kq + 2][m] = v.z; As[kq + 3][m] = v.w;
        }
#pragma unroll
        for (int r = 0; r < 4; r++) {   // load W tile: Bs[k][n]
            int k = (t >> 6) + (r << 2);
            int n = t & 63;
            Bs[k][n] = W[(k0 + k) * HD + n0 + n];
        }
        __syncthreads();
#pragma unroll
        for (int k = 0; k < 16; k++) {
            float a[4], b[4];
#pragma unroll
            for (int i = 0; i < 4; i++) a[i] = As[k][ty * 4 + i];
#pragma unroll
            for (int j = 0; j < 4; j++) b[j] = Bs[k][tx * 4 + j];
#pragma unroll
            for (int i = 0; i < 4; i++)
#pragma unroll
                for (int j = 0; j < 4; j++) acc[i][j] += a[i] * b[j];
        }
        __syncthreads();
    }
#pragma unroll
    for (int i = 0; i < 4; i++)
#pragma unroll
        for (int j = 0; j < 4; j++)
            g_h[(m0 + ty * 4 + i) * HD + n0 + tx * 4 + j] = acc[i][j];
}

// ---------------- K2: si/sj dots + exp factor precompute ----------------
__global__ __launch_bounds__(256) void scores(const float* __restrict__ a1,
                                              const float* __restrict__ a2) {
    int idx = blockIdx.x * blockDim.x + threadIdx.x;   // 0..NN*H-1
    if (idx >= NN * H) return;
    int n = idx >> 2, h = idx & 3;
    const float4* row = (const float4*)&g_h[n * HD + h * D];
    const float4* A1  = (const float4*)(a1);
    const float4* A2  = (const float4*)(a2);
    float s1 = 0.f, s2 = 0.f;
#pragma unroll
    for (int q = 0; q < D / 4; q++) {
        float4 v  = row[q];
        float4 c1 = __ldg(&A1[q]);
        float4 c2 = __ldg(&A2[q]);
        s1 += v.x * c1.x + v.y * c1.y + v.z * c1.z + v.w * c1.w;
        s2 += v.x * c2.x + v.y * c2.y + v.z * c2.z + v.w * c2.w;
    }
    g_si [idx] = s1;
    g_sj [idx] = s2;
    g_epi[idx] = __expf(s1);
    g_eni[idx] = __expf(0.2f * s1);
    g_epj[idx] = __expf(s2);
    g_enj[idx] = __expf(0.2f * s2);
}

// ---------------- K3: fused masked-softmax weights + aggregation ----------------
// block = 256 threads; block handles TI=16 destination rows, sweeps j in TJ=64 tiles.
// exp(leaky_relu(si+sj)) = (si+sj>0) ? exp(si)exp(sj) : exp(.2si)exp(.2sj)  -> no exp in loop
__global__ __launch_bounds__(256) void aggregate(const int* __restrict__ adj,
                                                 float* __restrict__ out) {
    __shared__ float si_s [TI * H], epi_s[TI * H], eni_s[TI * H];
    __shared__ float sj_s [TJ * H], epj_s[TJ * H], enj_s[TJ * H];
    __shared__ float wbuf [TJ * 68];          // row stride 68 floats (16B aligned, bank-spread)
    __shared__ float Zs   [TI * H];           // indexed (h<<4)|i

    const int t  = threadIdx.x;
    const int i0 = blockIdx.x * TI;

    // main-loop identity: one feature per thread
    const int hF = t >> 6;                    // head
    // w-phase identity: pair p=(i,h), 4 threads per pair
    const int p  = t >> 2;
    const int il = p & 15;
    const int hh = p >> 4;
    const int jj = t & 3;

    if (t < TI * H) {
        si_s [t] = g_si [i0 * H + t];
        epi_s[t] = g_epi[i0 * H + t];
        eni_s[t] = g_eni[i0 * H + t];
        Zs[t] = 0.f;
    }
    __syncthreads();

    const float siv  = si_s [il * H + hh];
    const float epiv = epi_s[il * H + hh];
    const float eniv = eni_s[il * H + hh];

    float acc[TI];
#pragma unroll
    for (int i = 0; i < TI; i++) acc[i] = 0.f;

    for (int jt = 0; jt < NN / TJ; jt++) {
        const int j0 = jt * TJ;
        __syncthreads();                       // wbuf free to overwrite
        // stage sj tile (TJ*H = 256 elements per array, fully coalesced)
        sj_s [t] = g_sj [j0 * H + t];
        epj_s[t] = g_epj[j0 * H + t];
        enj_s[t] = g_enj[j0 * H + t];
        __syncthreads();

        // ---- weight generation ----
        float zp = 0.f;
        const int* arow = adj + (long)(i0 + il) * NN + j0;
#pragma unroll
        for (int k = 0; k < 16; k++) {
            const int jl = jj + (k << 2);
            const int av = arow[jl];
            const float s = siv + sj_s[jl * H + hh];
            float w = 0.f;
            if (av > 0)
                w = (s > 0.f) ? epiv * epj_s[jl * H + hh]
                              : eniv * enj_s[jl * H + hh];
            wbuf[jl * 68 + (hh << 4) + il] = w;
            zp += w;
        }
        zp += __shfl_xor_sync(0xffffffffu, zp, 1);
        zp += __shfl_xor_sync(0xffffffffu, zp, 2);
        if (jj == 0) Zs[(hh << 4) + il] += zp;
        __syncthreads();

        // ---- aggregation: acc[i] += w[i][j][h] * h[j][f] ----
        const float* hcol = g_h + (long)j0 * HD + t;
        const float* wrow = wbuf + (hF << 4);
#pragma unroll 4
        for (int jl = 0; jl < TJ; jl++) {
            const float hv = hcol[(long)jl * HD];
            const float4* wp = (const float4*)(wrow + jl * 68);
            float4 w0 = wp[0], w1 = wp[1], w2 = wp[2], w3 = wp[3];
            acc[0]  += w0.x * hv;  acc[1]  += w0.y * hv;
            acc[2]  += w0.z * hv;  acc[3]  += w0.w * hv;
            acc[4]  += w1.x * hv;  acc[5]  += w1.y * hv;
            acc[6]  += w1.z * hv;  acc[7]  += w1.w * hv;
            acc[8]  += w2.x * hv;  acc[9]  += w2.y * hv;
            acc[10] += w2.z * hv;  acc[11] += w2.w * hv;
            acc[12] += w3.x * hv;  acc[13] += w3.y * hv;
            acc[14] += w3.z * hv;  acc[15] += w3.w * hv;
        }
    }
    __syncthreads();

    // ---- epilogue: normalize and store ----
#pragma unroll
    for (int i = 0; i < TI; i++) {
        const float z = Zs[(hF << 4) + i];
        out[(long)(i0 + i) * HD + t] = __fdividef(acc[i], z);
    }
}

extern "C" void kernel_launch(void* const* d_in, const int* in_sizes, int n_in,
                              void* d_out, int out_size) {
    const float* x   = (const float*)d_in[0];
    const int*   adj = (const int*)  d_in[1];
    const float* W   = (const float*)d_in[2];
    const float* a1  = (const float*)d_in[3];
    const float* a2  = (const float*)d_in[4];
    float* out = (float*)d_out;

    gemm_xw  <<<dim3(HD / 64, NN / 64), 256>>>(x, W);
    scores   <<<(NN * H) / 256, 256>>>(a1, a2);
    aggregate<<<NN / TI, 256>>>(adj, out);
}

// round 9
// speedup vs baseline: 3.0323x; 3.0253x over previous
#include <cuda_runtime.h>
#include <cuda_fp16.h>
#include <cuda_bf16.h>
#include <cstdint>

#define NN   4096
#define INF  256
#define HD   256   // H*D
#define H    4
#define D    64

// ---------------- device scratch (no cudaMalloc allowed) ----------------
__device__ float  g_h [NN * HD];                         // x@W, fp32
__device__ float4 g_fi[H * NN];                          // (si, e^si, e^.2si, 0)
__device__ float4 g_fj[H * NN];                          // (sj, e^sj, e^.2sj, 0)
__device__ __align__(16) __half g_ht[H * D * NN];        // h transposed per head: [h][f][j]

// ---------------- smem layout for aggregate_mma (bytes) ----------------
// padded row stride: 136 halfs = 272 B (keeps fragment loads conflict-free)
#define PSB   272
#define SM_FJS 0                      // float4[130] (skewed) = 2080
#define SM_ZS  2080                   // float[128] = 512
#define SM_AS  2592                   // 128 x 272B = 34816
#define SM_BS  (SM_AS + 128 * PSB)    // 37408; 64 x 272B = 17408
#define SM_TOT (SM_BS + 64 * PSB)     // 54816

__device__ __forceinline__ void mma16816(float* c,
                                         uint32_t a0, uint32_t a1, uint32_t a2, uint32_t a3,
                                         uint32_t b0, uint32_t b1) {
    asm volatile(
        "mma.sync.aligned.m16n8k16.row.col.f32.f16.f16.f32 "
        "{%0,%1,%2,%3}, {%4,%5,%6,%7}, {%8,%9}, {%0,%1,%2,%3};"
        : "+f"(c[0]), "+f"(c[1]), "+f"(c[2]), "+f"(c[3])
        : "r"(a0), "r"(a1), "r"(a2), "r"(a3), "r"(b0), "r"(b1));
}

// ---------------- K1: h = x @ W  (4096x256 @ 256x256) ----------------
__global__ __launch_bounds__(256) void gemm_xw(const float* __restrict__ x,
                                               const float* __restrict__ W) {
    __shared__ float As[16][65];
    __shared__ float Bs[16][64];
    const int t  = threadIdx.x;
    const int tx = t & 15, ty = t >> 4;
    const int m0 = blockIdx.y * 64;
    const int n0 = blockIdx.x * 64;

    float acc[4][4];
#pragma unroll
    for (int i = 0; i < 4; i++)
#pragma unroll
        for (int j = 0; j < 4; j++) acc[i][j] = 0.f;

    for (int k0 = 0; k0 < INF; k0 += 16) {
        {
            int m  = t >> 2;
            int kq = (t & 3) << 2;
            float4 v = *(const float4*)&x[(m0 + m) * INF + k0 + kq];
            As[kq + 0][m] = v.x; As[kq + 1][m] = v.y;
            As[kq + 2][m] = v.z; As[kq + 3][m] = v.w;
        }
#pragma unroll
        for (int r = 0; r < 4; r++) {
            int k = (t >> 6) + (r << 2);
            int n = t & 63;
            Bs[k][n] = W[(k0 + k) * HD + n0 + n];
        }
        __syncthreads();
#pragma unroll
        for (int k = 0; k < 16; k++) {
            float a[4], b[4];
#pragma unroll
            for (int i = 0; i < 4; i++) a[i] = As[k][ty * 4 + i];
#pragma unroll
            for (int j = 0; j < 4; j++) b[j] = Bs[k][tx * 4 + j];
#pragma unroll
            for (int i = 0; i < 4; i++)
#pragma unroll
                for (int j = 0; j < 4; j++) acc[i][j] += a[i] * b[j];
        }
        __syncthreads();
    }
#pragma unroll
    for (int i = 0; i < 4; i++)
#pragma unroll
        for (int j = 0; j < 4; j++)
            g_h[(m0 + ty * 4 + i) * HD + n0 + tx * 4 + j] = acc[i][j];
}

// ---------------- K2: score dots + packed exp factors ----------------
__global__ __launch_bounds__(256) void scores(const float* __restrict__ a1,
                                              const float* __restrict__ a2) {
    int idx = blockIdx.x * blockDim.x + threadIdx.x;
    if (idx >= NN * H) return;
    int n = idx >> 2, h = idx & 3;
    const float4* row = (const float4*)&g_h[n * HD + h * D];
    const float4* A1  = (const float4*)(a1);
    const float4* A2  = (const float4*)(a2);
    float s1 = 0.f, s2 = 0.f;
#pragma unroll
    for (int q = 0; q < D / 4; q++) {
        float4 v  = row[q];
        float4 c1 = __ldg(&A1[q]);
        float4 c2 = __ldg(&A2[q]);
        s1 += v.x * c1.x + v.y * c1.y + v.z * c1.z + v.w * c1.w;
        s2 += v.x * c2.x + v.y * c2.y + v.z * c2.z + v.w * c2.w;
    }
    g_fi[h * NN + n] = make_float4(s1, __expf(s1), __expf(0.2f * s1), 0.f);
    g_fj[h * NN + n] = make_float4(s2, __expf(s2), __expf(0.2f * s2), 0.f);
}

// ---------------- K2b: transposed fp16 features ht[h][f][j] ----------------
__global__ __launch_bounds__(256) void ht_build() {
    int gid = blockIdx.x * blockDim.x + threadIdx.x;   // H*D*NN = 1M
    if (gid >= H * D * NN) return;
    int j  = gid & (NN - 1);
    int fh = gid >> 12;
    int f  = fh & 63;
    int h  = fh >> 6;
    g_ht[gid] = __float2half(g_h[j * HD + h * D + f]);
}

// ---------------- K3: HMMA masked-softmax attention aggregation ----------------
// CTA = (i-tile of 128 rows, head). 8 warps; warp w owns rows [16w,16w+16), n=64.
__global__ __launch_bounds__(256, 1) void aggregate_mma(const int* __restrict__ adj,
                                                        float* __restrict__ out) {
    extern __shared__ char sm[];
    float4* fjs = (float4*)(sm + SM_FJS);   // skewed: index j + (j>>6)
    float*  Zs  = (float*) (sm + SM_ZS);
    char*   Ab  = sm + SM_AS;               // A: [128 i][128 j] fp16, stride 272B
    char*   Bb  = sm + SM_BS;               // B: [64 f][128 j] fp16, stride 272B

    const int t    = threadIdx.x;
    const int wid  = t >> 5, lane = t & 31;
    const int head = blockIdx.x & 3;
    const int i0   = (blockIdx.x >> 2) << 7;

    // gen identity: row il, j-half jh
    const int il = t >> 1;
    const int jh = (t & 1) << 6;
    const float4 fi = __ldg(&g_fi[head * NN + i0 + il]);
    const float negsi = -fi.x, epiv = fi.y, eniv = fi.z;
    const int* __restrict__ arow = adj + (size_t)(i0 + il) * NN + jh;
    char* const agen = Ab + il * PSB + jh * 2;

    // mma identity
    const int g  = lane >> 2;               // row-in-16 / n-in-8
    const int t2 = (lane & 3) << 1;         // k pair base
    char* const arow0 = Ab + (wid * 16 + g) * PSB;
    char* const arow1 = arow0 + 8 * PSB;

    float acc[8][4];
#pragma unroll
    for (int nb = 0; nb < 8; nb++)
#pragma unroll
        for (int q = 0; q < 4; q++) acc[nb][q] = 0.f;
    float zacc = 0.f;

    for (int c = 0; c < 32; ++c) {
        const int j0 = c << 7;
        __syncthreads();   // previous chunk's mma reads done -> safe to rewrite tiles

        // stage per-chunk j factors (skewed to avoid even/odd-half bank clash)
        if (t < 128) fjs[t + (t >> 6)] = __ldg(&g_fj[head * NN + j0 + t]);

        // stage B tile: Ht[f][j0..j0+128) fp16 -> Bb[f][*], 4 x uint4 per thread
#pragma unroll
        for (int r = 0; r < 4; ++r) {
            int idx = t + (r << 8);
            int f = idx >> 4, u = idx & 15;
            uint4 v = __ldg((const uint4*)(g_ht + ((size_t)(head * D + f) << 12) + j0) + u);
            *(uint4*)(Bb + f * PSB + u * 16) = v;
        }
        __syncthreads();

        // generate A tile: w[i][j] fp16 (64 weights per thread)
        {
            const int4* a4 = (const int4*)(arow + j0);
#pragma unroll
            for (int gg = 0; gg < 8; ++gg) {
                uint32_t pk[4];
#pragma unroll
                for (int hh = 0; hh < 2; ++hh) {
                    int4 av = __ldg(&a4[(gg << 1) + hh]);
                    int jb = jh + (gg << 3) + (hh << 2);
                    int js = jb + (jb >> 6);
                    float4 q0 = fjs[js + 0];
                    float4 q1 = fjs[js + 1];
                    float4 q2 = fjs[js + 2];
                    float4 q3 = fjs[js + 3];
                    float w0 = (q0.x > negsi) ? epiv * q0.y : eniv * q0.z;
                    float w1 = (q1.x > negsi) ? epiv * q1.y : eniv * q1.z;
                    float w2 = (q2.x > negsi) ? epiv * q2.y : eniv * q2.z;
                    float w3 = (q3.x > negsi) ? epiv * q3.y : eniv * q3.z;
                    w0 = (av.x > 0) ? w0 : 0.f;
                    w1 = (av.y > 0) ? w1 : 0.f;
                    w2 = (av.z > 0) ? w2 : 0.f;
                    w3 = (av.w > 0) ? w3 : 0.f;
                    zacc += (w0 + w1) + (w2 + w3);
                    __half2 p0 = __floats2half2_rn(w0, w1);
                    __half2 p1 = __floats2half2_rn(w2, w3);
                    pk[(hh << 1) + 0] = *(uint32_t*)&p0;
                    pk[(hh << 1) + 1] = *(uint32_t*)&p1;
                }
                *(uint4*)(agen + (gg << 4)) = make_uint4(pk[0], pk[1], pk[2], pk[3]);
            }
        }
        __syncthreads();

        // HMMA: 8 k-steps x 8 n-blocks
#pragma unroll
        for (int ks = 0; ks < 8; ++ks) {
            const int kb = (ks << 5) + (t2 << 1);   // byte offset of k0+t2 in fp16 row
            uint32_t a0 = *(const uint32_t*)(arow0 + kb);
            uint32_t a1 = *(const uint32_t*)(arow1 + kb);
            uint32_t a2 = *(const uint32_t*)(arow0 + kb + 16);
            uint32_t a3 = *(const uint32_t*)(arow1 + kb + 16);
#pragma unroll
            for (int nb = 0; nb < 8; ++nb) {
                const char* bp = Bb + (nb * 8 + g) * PSB + kb;
                uint32_t b0 = *(const uint32_t*)(bp);
                uint32_t b1 = *(const uint32_t*)(bp + 16);
                mma16816(acc[nb], a0, a1, a2, a3, b0, b1);
            }
        }
    }

    // finalize Z per destination row
    zacc += __shfl_xor_sync(0xffffffffu, zacc, 1);
    if ((t & 1) == 0) Zs[il] = zacc;
    __syncthreads();

    // epilogue: normalize + store (float2 per fragment row)
    const int r0 = wid * 16 + g;
    const float rz0 = 1.0f / Zs[r0];
    const float rz1 = 1.0f / Zs[r0 + 8];
    float* const ob = out + (size_t)(i0 + r0) * HD + (head << 6) + t2;
#pragma unroll
    for (int nb = 0; nb < 8; ++nb) {
        *(float2*)(ob + nb * 8)            = make_float2(acc[nb][0] * rz0, acc[nb][1] * rz0);
        *(float2*)(ob + nb * 8 + 8 * HD)   = make_float2(acc[nb][2] * rz1, acc[nb][3] * rz1);
    }
}

extern "C" void kernel_launch(void* const* d_in, const int* in_sizes, int n_in,
                              void* d_out, int out_size) {
    const float* x   = (const float*)d_in[0];
    const int*   adj = (const int*)  d_in[1];
    const float* W   = (const float*)d_in[2];
    const float* a1  = (const float*)d_in[3];
    const float* a2  = (const float*)d_in[4];
    float* out = (float*)d_out;

    cudaFuncSetAttribute(aggregate_mma, cudaFuncAttributeMaxDynamicSharedMemorySize, SM_TOT);

    gemm_xw      <<<dim3(HD / 64, NN / 64), 256>>>(x, W);
    scores       <<<(NN * H) / 256, 256>>>(a1, a2);
    ht_build     <<<(H * D * NN) / 256, 256>>>();
    aggregate_mma<<<NN / 32, 256, SM_TOT>>>(adj, out);
}

// round 10
// speedup vs baseline: 3.1864x; 1.0508x over previous
#include <cuda_runtime.h>
#include <cuda_fp16.h>
#include <cstdint>

#define NN   4096
#define INF  256
#define HD   256   // H*D
#define H    4
#define D    64

// ---------------- device scratch (no cudaMalloc allowed) ----------------
__device__ float  g_h [NN * HD];                   // x@W, fp32
__device__ float4 g_fi[H * NN];                    // (si, e^si, e^.2si, 0) fp32
__device__ __align__(16) uint4  g_fjp[H * NN / 2]; // per (h, j-pair): {sj2, e^sj 2, e^.2sj 2, 0} half2 bits
__device__ __align__(16) __half g_ht[H * D * NN];  // h transposed per head: [h][f][j]

// ---------------- smem layout for aggregate_mma (bytes) ----------------
#define PSB    272                    // padded row stride (136 halfs)
#define SM_FJP 0                      // uint4[64] = 1024
#define SM_AS  1024                   // 64 x 272 = 17408 -> 18432
#define SM_BS  18432                  // 72 x 272 = 19584 -> 38016 (rows 64..71: ones/zero)
#define SM_TOT 38016

__device__ __forceinline__ uint32_t smem_u32(const void* p) {
    uint32_t a;
    asm("{ .reg .u64 t; cvta.to.shared.u64 t, %1; cvt.u32.u64 %0, t; }"
        : "=r"(a) : "l"(p));
    return a;
}

__device__ __forceinline__ void mma16816(float* c,
                                         uint32_t a0, uint32_t a1, uint32_t a2, uint32_t a3,
                                         uint32_t b0, uint32_t b1) {
    asm volatile(
        "mma.sync.aligned.m16n8k16.row.col.f32.f16.f16.f32 "
        "{%0,%1,%2,%3}, {%4,%5,%6,%7}, {%8,%9}, {%0,%1,%2,%3};"
        : "+f"(c[0]), "+f"(c[1]), "+f"(c[2]), "+f"(c[3])
        : "r"(a0), "r"(a1), "r"(a2), "r"(a3), "r"(b0), "r"(b1));
}

__device__ __forceinline__ void ldsm4(uint32_t& r0, uint32_t& r1, uint32_t& r2, uint32_t& r3,
                                      uint32_t addr) {
    asm volatile("ldmatrix.sync.aligned.m8n8.x4.shared.b16 {%0,%1,%2,%3}, [%4];"
                 : "=r"(r0), "=r"(r1), "=r"(r2), "=r"(r3) : "r"(addr));
}

__device__ __forceinline__ void ldsm2(uint32_t& r0, uint32_t& r1, uint32_t addr) {
    asm volatile("ldmatrix.sync.aligned.m8n8.x2.shared.b16 {%0,%1}, [%2];"
                 : "=r"(r0), "=r"(r1) : "r"(addr));
}

__device__ __forceinline__ __half2 h2bits(uint32_t v) { return *(__half2*)&v; }
__device__ __forceinline__ uint32_t bitsh2(__half2 v) { return *(uint32_t*)&v; }

// 2 masked weights: w = adj * ((sj > -si) ? e^si*e^sj : e^.2si*e^.2sj), packed half2
__device__ __forceinline__ uint32_t wcalc(uint4 q, int ax, int ay,
                                          __half2 negsi2, __half2 epi2, __half2 eni2) {
    __half2 cond = __hgt2(h2bits(q.x), negsi2);      // 1.0 / 0.0 per lane
    __half2 ph   = __hmul2(epi2, h2bits(q.y));
    __half2 pl   = __hmul2(eni2, h2bits(q.z));
    __half2 w    = __hfma2(cond, __hsub2(ph, pl), pl);
    uint32_t mb  = (uint32_t)(ax + (ay << 16)) * 0x3C00u;  // {0,1}->half 1.0 per lane
    return bitsh2(__hmul2(w, h2bits(mb)));
}

// ---------------- K1: h = x @ W, fused fp16 transpose epilogue ----------------
__global__ __launch_bounds__(256) void gemm_xw(const float* __restrict__ x,
                                               const float* __restrict__ W) {
    __shared__ float As[16][65];
    __shared__ float Bs[16][64];
    __shared__ __half Ts[64][80];      // transpose bounce, 160B rows (16B aligned)
    const int t  = threadIdx.x;
    const int tx = t & 15, ty = t >> 4;
    const int m0 = blockIdx.y * 64;
    const int n0 = blockIdx.x * 64;    // blockIdx.x == head (HD/64 == H)

    float acc[4][4];
#pragma unroll
    for (int i = 0; i < 4; i++)
#pragma unroll
        for (int j = 0; j < 4; j++) acc[i][j] = 0.f;

    for (int k0 = 0; k0 < INF; k0 += 16) {
        {
            int m  = t >> 2;
            int kq = (t & 3) << 2;
            float4 v = *(const float4*)&x[(m0 + m) * INF + k0 + kq];
            As[kq + 0][m] = v.x; As[kq + 1][m] = v.y;
            As[kq + 2][m] = v.z; As[kq + 3][m] = v.w;
        }
#pragma unroll
        for (int r = 0; r < 4; r++) {
            int k = (t >> 6) + (r << 2);
            int n = t & 63;
            Bs[k][n] = W[(k0 + k) * HD + n0 + n];
        }
        __syncthreads();
#pragma unroll
        for (int k = 0; k < 16; k++) {
            float a[4], b[4];
#pragma unroll
            for (int i = 0; i < 4; i++) a[i] = As[k][ty * 4 + i];
#pragma unroll
            for (int j = 0; j < 4; j++) b[j] = Bs[k][tx * 4 + j];
#pragma unroll
            for (int i = 0; i < 4; i++)
#pragma unroll
                for (int j = 0; j < 4; j++) acc[i][j] += a[i] * b[j];
        }
        __syncthreads();
    }
#pragma unroll
    for (int i = 0; i < 4; i++)
#pragma unroll
        for (int j = 0; j < 4; j++) {
            g_h[(m0 + ty * 4 + i) * HD + n0 + tx * 4 + j] = acc[i][j];
            Ts[tx * 4 + j][ty * 4 + i] = __float2half(acc[i][j]);
        }
    __syncthreads();
    // coalesced fp16 transposed store: g_ht[head][f][m]
#pragma unroll
    for (int r = 0; r < 2; ++r) {
        int id = t + (r << 8);         // 0..511
        int f  = id >> 3, u = id & 7;
        uint4 v = *(const uint4*)&Ts[f][u * 8];
        *(uint4*)(g_ht + (((size_t)(blockIdx.x * 64 + f)) << 12) + m0 + u * 8) = v;
    }
}

// ---------------- K2: score dots + fp32/fp16 exp factor precompute ----------------
__global__ __launch_bounds__(256) void scores(const float* __restrict__ a1,
                                              const float* __restrict__ a2) {
    int idx = blockIdx.x * blockDim.x + threadIdx.x;   // 0 .. NN*H/2-1
    if (idx >= NN * H / 2) return;
    int h = idx & 3, p = idx >> 2;
    int n0 = p << 1;
    const float4* r0 = (const float4*)&g_h[(size_t)n0 * HD + h * D];
    const float4* r1 = (const float4*)&g_h[(size_t)(n0 + 1) * HD + h * D];
    const float4* A1 = (const float4*)(a1);
    const float4* A2 = (const float4*)(a2);
    float s1a = 0.f, s2a = 0.f, s1b = 0.f, s2b = 0.f;
#pragma unroll
    for (int q = 0; q < D / 4; q++) {
        float4 v0 = r0[q], v1 = r1[q];
        float4 c1 = __ldg(&A1[q]);
        float4 c2 = __ldg(&A2[q]);
        s1a += v0.x * c1.x + v0.y * c1.y + v0.z * c1.z + v0.w * c1.w;
        s2a += v0.x * c2.x + v0.y * c2.y + v0.z * c2.z + v0.w * c2.w;
        s1b += v1.x * c1.x + v1.y * c1.y + v1.z * c1.z + v1.w * c1.w;
        s2b += v1.x * c2.x + v1.y * c2.y + v1.z * c2.z + v1.w * c2.w;
    }
    g_fi[h * NN + n0]     = make_float4(s1a, __expf(s1a), __expf(0.2f * s1a), 0.f);
    g_fi[h * NN + n0 + 1] = make_float4(s1b, __expf(s1b), __expf(0.2f * s1b), 0.f);
    uint4 o;
    o.x = bitsh2(__floats2half2_rn(s2a, s2b));
    o.y = bitsh2(__floats2half2_rn(__expf(s2a), __expf(s2b)));
    o.z = bitsh2(__floats2half2_rn(__expf(0.2f * s2a), __expf(0.2f * s2b)));
    o.w = 0;
    g_fjp[h * (NN / 2) + p] = o;
}

// ---------------- K3: HMMA masked-softmax aggregation (Z via ones-column) ----------------
// CTA = (64 i-rows, head), 128 threads / 4 warps; warp w owns rows [16w,16w+16), n=0..63 (+Z col 64).
__global__ __launch_bounds__(128, 2) void aggregate_mma(const int* __restrict__ adj,
                                                        float* __restrict__ out) {
    extern __shared__ char sm[];
    uint4* fjp = (uint4*)(sm + SM_FJP);
    char*  Ab  = sm + SM_AS;
    char*  Bb  = sm + SM_BS;

    const int t    = threadIdx.x;
    const int lane = t & 31, wid = t >> 5;
    const int head = blockIdx.x & 3;
    const int i0   = (blockIdx.x >> 2) << 6;

    // init B rows 64..71 once: row 64 = ones (Z column), 65..71 = zeros
    for (int k = t; k < 136; k += 128) {
        int r = k / 17, u = k - r * 17;
        uint32_t one = (r == 0) ? 0x3C003C00u : 0u;
        *(uint4*)(Bb + (64 + r) * PSB + u * 16) = make_uint4(one, one, one, one);
    }

    // gen identity: row il, j-half jh
    const int il = t >> 1;
    const int jh = (t & 1) << 6;
    const float4 fi = __ldg(&g_fi[head * NN + i0 + il]);
    const __half2 negsi2 = __float2half2_rn(-fi.x);
    const __half2 epi2   = __float2half2_rn(fi.y);
    const __half2 eni2   = __float2half2_rn(fi.z);
    const int* __restrict__ arow = adj + (size_t)(i0 + il) * NN + jh;
    char* const agen = Ab + il * PSB + (jh << 1);

    // mma identity
    const int g  = lane >> 2;
    const int t2 = (lane & 3) << 1;
    const uint32_t Ab_u = smem_u32(Ab), Bb_u = smem_u32(Bb);
    const uint32_t lrow = ((lane >> 3) & 1) * 8 + (lane & 7);
    const uint32_t lcol = (lane >> 4) * 16;
    const uint32_t a_base  = Ab_u + (wid * 16 + lrow) * PSB + lcol;
    const uint32_t b_base0 = Bb_u + (lrow +  0) * PSB + lcol;
    const uint32_t b_base1 = Bb_u + (lrow + 16) * PSB + lcol;
    const uint32_t b_base2 = Bb_u + (lrow + 32) * PSB + lcol;
    const uint32_t b_base3 = Bb_u + (lrow + 48) * PSB + lcol;
    const uint32_t bz_base = Bb_u + (64 + (lane & 7)) * PSB + ((lane >> 3) & 1) * 16;

    float acc[8][4];
    float accz[4];
#pragma unroll
    for (int nb = 0; nb < 8; nb++)
#pragma unroll
        for (int q = 0; q < 4; q++) acc[nb][q] = 0.f;
#pragma unroll
    for (int q = 0; q < 4; q++) accz[q] = 0.f;

    for (int c = 0; c < 32; ++c) {
        const int j0c = c << 7;
        __syncthreads();                        // prior mma reads done

        if (t < 64) fjp[t] = __ldg(&g_fjp[head * (NN / 2) + (j0c >> 1) + t]);

        // stage B tile rows 0..63: Ht[f][j0c..+128)
#pragma unroll
        for (int r = 0; r < 8; ++r) {
            int id = t + (r << 7);
            int f  = id >> 4, u = id & 15;
            uint4 v = __ldg((const uint4*)(g_ht + (((size_t)(head * D + f)) << 12) + j0c) + u);
            *(uint4*)(Bb + f * PSB + (u << 4)) = v;
        }
        __syncthreads();

        // generate A tile: 64 masked weights per thread, half2 math
        {
            const int4*  a4 = (const int4*)(arow + j0c);
            const uint4* fq = fjp + (jh >> 1);
#pragma unroll
            for (int gg = 0; gg < 8; ++gg) {
                int4 av0 = __ldg(&a4[gg * 2]);
                int4 av1 = __ldg(&a4[gg * 2 + 1]);
                uint4 q0 = fq[gg * 4 + 0];
                uint4 q1 = fq[gg * 4 + 1];
                uint4 q2 = fq[gg * 4 + 2];
                uint4 q3 = fq[gg * 4 + 3];
                uint4 pk;
                pk.x = wcalc(q0, av0.x, av0.y, negsi2, epi2, eni2);
                pk.y = wcalc(q1, av0.z, av0.w, negsi2, epi2, eni2);
                pk.z = wcalc(q2, av1.x, av1.y, negsi2, epi2, eni2);
                pk.w = wcalc(q3, av1.z, av1.w, negsi2, epi2, eni2);
                *(uint4*)(agen + (gg << 4)) = pk;
            }
        }
        __syncthreads();

        // HMMA: 8 k-steps, 8 n-blocks + Z column
#pragma unroll
        for (int ks = 0; ks < 8; ++ks) {
            const uint32_t ko = ks * 32;
            uint32_t a0, a1, a2, a3, b0, b1, b2, b3, z0, z1;
            ldsm4(a0, a1, a2, a3, a_base + ko);
            ldsm4(b0, b1, b2, b3, b_base0 + ko);
            mma16816(acc[0], a0, a1, a2, a3, b0, b2);
            mma16816(acc[1], a0, a1, a2, a3, b1, b3);
            ldsm4(b0, b1, b2, b3, b_base1 + ko);
            mma16816(acc[2], a0, a1, a2, a3, b0, b2);
            mma16816(acc[3], a0, a1, a2, a3, b1, b3);
            ldsm4(b0, b1, b2, b3, b_base2 + ko);
            mma16816(acc[4], a0, a1, a2, a3, b0, b2);
            mma16816(acc[5], a0, a1, a2, a3, b1, b3);
            ldsm4(b0, b1, b2, b3, b_base3 + ko);
            mma16816(acc[6], a0, a1, a2, a3, b0, b2);
            mma16816(acc[7], a0, a1, a2, a3, b1, b3);
            ldsm2(z0, z1, bz_base + ko);
            mma16816(accz, a0, a1, a2, a3, z0, z1);
        }
    }

    // Z lives in column n=64: lane (g<<2) holds Z(r0) in accz[0], Z(r0+8) in accz[2]
    const float z0 = __shfl_sync(0xffffffffu, accz[0], lane & ~3);
    const float z1 = __shfl_sync(0xffffffffu, accz[2], lane & ~3);
    const float rz0 = 1.0f / z0;
    const float rz1 = 1.0f / z1;

    const int r0 = wid * 16 + g;
    float* const ob = out + (size_t)(i0 + r0) * HD + (head << 6) + t2;
#pragma unroll
    for (int nb = 0; nb < 8; ++nb) {
        *(float2*)(ob + nb * 8)          = make_float2(acc[nb][0] * rz0, acc[nb][1] * rz0);
        *(float2*)(ob + nb * 8 + 8 * HD) = make_float2(acc[nb][2] * rz1, acc[nb][3] * rz1);
    }
}

extern "C" void kernel_launch(void* const* d_in, const int* in_sizes, int n_in,
                              void* d_out, int out_size) {
    const float* x   = (const float*)d_in[0];
    const int*   adj = (const int*)  d_in[1];
    const float* W   = (const float*)d_in[2];
    const float* a1  = (const float*)d_in[3];
    const float* a2  = (const float*)d_in[4];
    float* out = (float*)d_out;

    cudaFuncSetAttribute(aggregate_mma, cudaFuncAttributeMaxDynamicSharedMemorySize, SM_TOT);

    gemm_xw      <<<dim3(HD / 64, NN / 64), 256>>>(x, W);
    scores       <<<(NN * H / 2) / 256, 256>>>(a1, a2);
    aggregate_mma<<<(NN / 64) * H, 128, SM_TOT>>>(adj, out);
}

// round 11
// speedup vs baseline: 4.8219x; 1.5133x over previous
#include <cuda_runtime.h>
#include <cuda_fp16.h>
#include <cstdint>

#define NN   4096
#define INF  256
#define HD   256   // H*D
#define H    4
#define D    64

// ---------------- device scratch (no cudaMalloc allowed) ----------------
__device__ float    g_h  [NN * HD];                  // x@W, fp32
__device__ float4   g_fi [H * NN];                   // (si, e^si, e^.2si, 0) fp32
__device__ __align__(16) uint4  g_fjp[H * NN / 2];   // per (h, j-pair): {sj2, e^sj2, e^.2sj2, 0}
__device__ __align__(16) __half g_ht [H * D * NN];   // h transposed per head: [h][f][j]
__device__ __align__(16) uint32_t g_adjb[NN * NN / 32];  // packed adjacency bits

// ---------------- smem layout for aggregate_mma (bytes) ----------------
#define PSB    272                    // padded B/A row stride (136 halfs)
#define BBUF   19584                  // one B buffer: 72 rows x 272
#define SM_FJP 0                      // 3 x uint4[64] = 3072
#define SM_AS  3072                   // A: 64 x 272 = 17408
#define SM_BS  20480                  // 3 x 19584 = 58752
#define SM_TOT 79232

__device__ __forceinline__ uint32_t smem_u32(const void* p) {
    uint32_t a;
    asm("{ .reg .u64 t; cvta.to.shared.u64 t, %1; cvt.u32.u64 %0, t; }"
        : "=r"(a) : "l"(p));
    return a;
}

__device__ __forceinline__ void cpa16(uint32_t dst, const void* src) {
    asm volatile("cp.async.cg.shared.global [%0], [%1], 16;" :: "r"(dst), "l"(src));
}

__device__ __forceinline__ void mma16816(float* c,
                                         uint32_t a0, uint32_t a1, uint32_t a2, uint32_t a3,
                                         uint32_t b0, uint32_t b1) {
    asm volatile(
        "mma.sync.aligned.m16n8k16.row.col.f32.f16.f16.f32 "
        "{%0,%1,%2,%3}, {%4,%5,%6,%7}, {%8,%9}, {%0,%1,%2,%3};"
        : "+f"(c[0]), "+f"(c[1]), "+f"(c[2]), "+f"(c[3])
        : "r"(a0), "r"(a1), "r"(a2), "r"(a3), "r"(b0), "r"(b1));
}

__device__ __forceinline__ void ldsm4(uint32_t& r0, uint32_t& r1, uint32_t& r2, uint32_t& r3,
                                      uint32_t addr) {
    asm volatile("ldmatrix.sync.aligned.m8n8.x4.shared.b16 {%0,%1,%2,%3}, [%4];"
                 : "=r"(r0), "=r"(r1), "=r"(r2), "=r"(r3) : "r"(addr));
}

__device__ __forceinline__ void ldsm2(uint32_t& r0, uint32_t& r1, uint32_t addr) {
    asm volatile("ldmatrix.sync.aligned.m8n8.x2.shared.b16 {%0,%1}, [%2];"
                 : "=r"(r0), "=r"(r1) : "r"(addr));
}

__device__ __forceinline__ __half2 h2bits(uint32_t v) { return *(__half2*)&v; }
__device__ __forceinline__ uint32_t bitsh2(__half2 v) { return *(uint32_t*)&v; }

// 2 masked weights from 2 adjacency bits (bb)
__device__ __forceinline__ uint32_t wcalc(uint4 q, uint32_t bb,
                                          __half2 negsi2, __half2 epi2, __half2 eni2) {
    __half2 cond = __hgt2(h2bits(q.x), negsi2);
    __half2 ph   = __hmul2(epi2, h2bits(q.y));
    __half2 pl   = __hmul2(eni2, h2bits(q.z));
    __half2 w    = __hfma2(cond, __hsub2(ph, pl), pl);
    uint32_t mb  = (bb & 1u) * 0x3C00u + (bb & 2u) * 0x1E000000u;  // {0,1}^2 -> half2 1.0 mask
    return bitsh2(__hmul2(w, h2bits(mb)));
}

// ---------------- K0: pack adjacency to bits ----------------
__global__ __launch_bounds__(256) void pack_adj(const int* __restrict__ adj) {
    const int w    = (blockIdx.x * blockDim.x + threadIdx.x) >> 5;   // global warp id
    const int lane = threadIdx.x & 31;
    const size_t base = (size_t)w << 7;                              // 128 ints per warp
    int v0 = __ldg(adj + base + lane);
    int v1 = __ldg(adj + base + 32 + lane);
    int v2 = __ldg(adj + base + 64 + lane);
    int v3 = __ldg(adj + base + 96 + lane);
    uint32_t b0 = __ballot_sync(0xffffffffu, v0 > 0);
    uint32_t b1 = __ballot_sync(0xffffffffu, v1 > 0);
    uint32_t b2 = __ballot_sync(0xffffffffu, v2 > 0);
    uint32_t b3 = __ballot_sync(0xffffffffu, v3 > 0);
    if (lane == 0)
        *(uint4*)&g_adjb[base >> 5] = make_uint4(b0, b1, b2, b3);
}

// ---------------- K1: h = x @ W, fused fp16 transpose epilogue ----------------
__global__ __launch_bounds__(256) void gemm_xw(const float* __restrict__ x,
                                               const float* __restrict__ W) {
    __shared__ float As[16][65];
    __shared__ float Bs[16][64];
    __shared__ __half Ts[64][80];
    const int t  = threadIdx.x;
    const int tx = t & 15, ty = t >> 4;
    const int m0 = blockIdx.y * 64;
    const int n0 = blockIdx.x * 64;

    float acc[4][4];
#pragma unroll
    for (int i = 0; i < 4; i++)
#pragma unroll
        for (int j = 0; j < 4; j++) acc[i][j] = 0.f;

    for (int k0 = 0; k0 < INF; k0 += 16) {
        {
            int m  = t >> 2;
            int kq = (t & 3) << 2;
            float4 v = *(const float4*)&x[(m0 + m) * INF + k0 + kq];
            As[kq + 0][m] = v.x; As[kq + 1][m] = v.y;
            As[kq + 2][m] = v.z; As[kq + 3][m] = v.w;
        }
#pragma unroll
        for (int r = 0; r < 4; r++) {
            int k = (t >> 6) + (r << 2);
            int n = t & 63;
            Bs[k][n] = W[(k0 + k) * HD + n0 + n];
        }
        __syncthreads();
#pragma unroll
        for (int k = 0; k < 16; k++) {
            float a[4], b[4];
#pragma unroll
            for (int i = 0; i < 4; i++) a[i] = As[k][ty * 4 + i];
#pragma unroll
            for (int j = 0; j < 4; j++) b[j] = Bs[k][tx * 4 + j];
#pragma unroll
            for (int i = 0; i < 4; i++)
#pragma unroll
                for (int j = 0; j < 4; j++) acc[i][j] += a[i] * b[j];
        }
        __syncthreads();
    }
#pragma unroll
    for (int i = 0; i < 4; i++)
#pragma unroll
        for (int j = 0; j < 4; j++) {
            g_h[(m0 + ty * 4 + i) * HD + n0 + tx * 4 + j] = acc[i][j];
            Ts[tx * 4 + j][ty * 4 + i] = __float2half(acc[i][j]);
        }
    __syncthreads();
#pragma unroll
    for (int r = 0; r < 2; ++r) {
        int id = t + (r << 8);
        int f  = id >> 3, u = id & 7;
        uint4 v = *(const uint4*)&Ts[f][u * 8];
        *(uint4*)(g_ht + (((size_t)(blockIdx.x * 64 + f)) << 12) + m0 + u * 8) = v;
    }
}

// ---------------- K2: score dots + exp factor precompute ----------------
__global__ __launch_bounds__(256) void scores(const float* __restrict__ a1,
                                              const float* __restrict__ a2) {
    int idx = blockIdx.x * blockDim.x + threadIdx.x;
    if (idx >= NN * H / 2) return;
    int h = idx & 3, p = idx >> 2;
    int n0 = p << 1;
    const float4* r0 = (const float4*)&g_h[(size_t)n0 * HD + h * D];
    const float4* r1 = (const float4*)&g_h[(size_t)(n0 + 1) * HD + h * D];
    const float4* A1 = (const float4*)(a1);
    const float4* A2 = (const float4*)(a2);
    float s1a = 0.f, s2a = 0.f, s1b = 0.f, s2b = 0.f;
#pragma unroll
    for (int q = 0; q < D / 4; q++) {
        float4 v0 = r0[q], v1 = r1[q];
        float4 c1 = __ldg(&A1[q]);
        float4 c2 = __ldg(&A2[q]);
        s1a += v0.x * c1.x + v0.y * c1.y + v0.z * c1.z + v0.w * c1.w;
        s2a += v0.x * c2.x + v0.y * c2.y + v0.z * c2.z + v0.w * c2.w;
        s1b += v1.x * c1.x + v1.y * c1.y + v1.z * c1.z + v1.w * c1.w;
        s2b += v1.x * c2.x + v1.y * c2.y + v1.z * c2.z + v1.w * c2.w;
    }
    g_fi[h * NN + n0]     = make_float4(s1a, __expf(s1a), __expf(0.2f * s1a), 0.f);
    g_fi[h * NN + n0 + 1] = make_float4(s1b, __expf(s1b), __expf(0.2f * s1b), 0.f);
    uint4 o;
    o.x = bitsh2(__floats2half2_rn(s2a, s2b));
    o.y = bitsh2(__floats2half2_rn(__expf(s2a), __expf(s2b)));
    o.z = bitsh2(__floats2half2_rn(__expf(0.2f * s2a), __expf(0.2f * s2b)));
    o.w = 0;
    g_fjp[h * (NN / 2) + p] = o;
}

// ---------------- K3: pipelined HMMA masked-softmax aggregation ----------------
// CTA = (64 i-rows, head), 128 threads / 4 warps. Triple-buffered cp.async B/fj tiles,
// adjacency bits prefetched in registers, Z via ones-column MMA.
__global__ __launch_bounds__(128, 2) void aggregate_mma(float* __restrict__ out) {
    extern __shared__ char sm[];
    uint4* fjp = (uint4*)(sm + SM_FJP);
    char*  Ab  = sm + SM_AS;
    char*  Bb  = sm + SM_BS;

    const int t    = threadIdx.x;
    const int lane = t & 31, wid = t >> 5;
    const int head = blockIdx.x & 3;
    const int i0   = (blockIdx.x >> 2) << 6;

    const uint32_t sm_u  = smem_u32(sm);
    const uint32_t fjp_u = sm_u + SM_FJP;
    const uint32_t Ab_u  = sm_u + SM_AS;
    const uint32_t Bb_u  = sm_u + SM_BS;

    // init ones/zero rows 64..71 of all 3 B buffers (row 64 = Z ones-column)
    for (int k = t; k < 3 * 136; k += 128) {
        int b  = k / 136, kk = k - b * 136;
        int r  = kk / 17, u  = kk - r * 17;
        uint32_t one = (r == 0) ? 0x3C003C00u : 0u;
        *(uint4*)(Bb + b * BBUF + (64 + r) * PSB + u * 16) = make_uint4(one, one, one, one);
    }

    // gen identity: row il, j-half jh
    const int il = t >> 1;
    const int jh = (t & 1) << 6;
    const float4 fi = __ldg(&g_fi[head * NN + i0 + il]);
    const __half2 negsi2 = __float2half2_rn(-fi.x);
    const __half2 epi2   = __float2half2_rn(fi.y);
    const __half2 eni2   = __float2half2_rn(fi.z);
    char* const agen = Ab + il * PSB + (jh << 1);
    const uint32_t* __restrict__ arow = g_adjb + ((size_t)(i0 + il) << 7) + (jh >> 5);

    // stage helper (issue cp.async group for chunk cc)
    auto stage = [&](int cc) {
        const int j0  = cc << 7;
        const int buf = cc % 3;
        if (t < 64)
            cpa16(fjp_u + buf * 1024 + t * 16,
                  (const char*)(g_fjp + head * (NN / 2) + (j0 >> 1) + t));
#pragma unroll
        for (int r = 0; r < 8; ++r) {
            int id = t + (r << 7);
            int f  = id >> 4, u = id & 15;
            cpa16(Bb_u + buf * BBUF + f * PSB + (u << 4),
                  g_ht + (((size_t)(head * D + f)) << 12) + j0 + u * 8);
        }
    };

    // prologue: chunks 0,1 in flight; adj words for chunk 0 in regs
    stage(0); asm volatile("cp.async.commit_group;");
    stage(1); asm volatile("cp.async.commit_group;");
    uint32_t aw0 = __ldg(arow + 0);
    uint32_t aw1 = __ldg(arow + 1);

    // mma identity
    const int g  = lane >> 2;
    const int t2 = (lane & 3) << 1;
    const uint32_t lrow = ((lane >> 3) & 1) * 8 + (lane & 7);
    const uint32_t lcol = (lane >> 4) * 16;
    const uint32_t a_base = Ab_u + (wid * 16 + lrow) * PSB + lcol;

    float acc[8][4];
    float accz[4];
#pragma unroll
    for (int nb = 0; nb < 8; nb++)
#pragma unroll
        for (int q = 0; q < 4; q++) acc[nb][q] = 0.f;
#pragma unroll
    for (int q = 0; q < 4; q++) accz[q] = 0.f;

    for (int c = 0; c < 32; ++c) {
        const int buf = c % 3;
        asm volatile("cp.async.wait_group 1;" ::: "memory");   // chunk c landed
        __syncthreads();                                       // publish tiles; A free

        // ---- generate A tile (64 masked weights / thread) ----
        {
            const uint4* fq = fjp + buf * 64 + (jh >> 1);
#pragma unroll
            for (int gg = 0; gg < 8; ++gg) {
                uint4 q0 = fq[gg * 4 + 0];
                uint4 q1 = fq[gg * 4 + 1];
                uint4 q2 = fq[gg * 4 + 2];
                uint4 q3 = fq[gg * 4 + 3];
                const uint32_t ws = (gg < 4) ? aw0 : aw1;
                const int sh = (gg & 3) << 3;
                uint4 pk;
                pk.x = wcalc(q0, (ws >> (sh + 0)) & 3u, negsi2, epi2, eni2);
                pk.y = wcalc(q1, (ws >> (sh + 2)) & 3u, negsi2, epi2, eni2);
                pk.z = wcalc(q2, (ws >> (sh + 4)) & 3u, negsi2, epi2, eni2);
                pk.w = wcalc(q3, (ws >> (sh + 6)) & 3u, negsi2, epi2, eni2);
                *(uint4*)(agen + (gg << 4)) = pk;
            }
        }
        // prefetch adjacency words for chunk c+1 (latency hidden behind MMA)
        uint32_t awn0 = 0, awn1 = 0;
        if (c < 31) {
            awn0 = __ldg(arow + ((c + 1) << 2));
            awn1 = __ldg(arow + ((c + 1) << 2) + 1);
        }
        __syncthreads();

        // ---- HMMA: 8 k-steps, 8 n-blocks + Z column ----
        const uint32_t Bu = Bb_u + buf * BBUF;
        const uint32_t b_base0 = Bu + (lrow +  0) * PSB + lcol;
        const uint32_t b_base1 = Bu + (lrow + 16) * PSB + lcol;
        const uint32_t b_base2 = Bu + (lrow + 32) * PSB + lcol;
        const uint32_t b_base3 = Bu + (lrow + 48) * PSB + lcol;
        const uint32_t bz_base = Bu + (64 + (lane & 7)) * PSB + ((lane >> 3) & 1) * 16;
#pragma unroll
        for (int ks = 0; ks < 8; ++ks) {
            const uint32_t ko = ks * 32;
            uint32_t a0, a1, a2, a3, b0, b1, b2, b3, z0, z1;
            ldsm4(a0, a1, a2, a3, a_base + ko);
            ldsm4(b0, b1, b2, b3, b_base0 + ko);
            mma16816(acc[0], a0, a1, a2, a3, b0, b2);
            mma16816(acc[1], a0, a1, a2, a3, b1, b3);
            ldsm4(b0, b1, b2, b3, b_base1 + ko);
            mma16816(acc[2], a0, a1, a2, a3, b0, b2);
            mma16816(acc[3], a0, a1, a2, a3, b1, b3);
            ldsm4(b0, b1, b2, b3, b_base2 + ko);
            mma16816(acc[4], a0, a1, a2, a3, b0, b2);
            mma16816(acc[5], a0, a1, a2, a3, b1, b3);
            ldsm4(b0, b1, b2, b3, b_base3 + ko);
            mma16816(acc[6], a0, a1, a2, a3, b0, b2);
            mma16816(acc[7], a0, a1, a2, a3, b1, b3);
            ldsm2(z0, z1, bz_base + ko);
            mma16816(accz, a0, a1, a2, a3, z0, z1);
        }

        // issue staging for chunk c+2 (into buffer just freed by MMA(c-1))
        if (c + 2 < 32) stage(c + 2);
        asm volatile("cp.async.commit_group;");

        aw0 = awn0; aw1 = awn1;
    }

    // Z from column n=64
    const float z0 = __shfl_sync(0xffffffffu, accz[0], lane & ~3);
    const float z1 = __shfl_sync(0xffffffffu, accz[2], lane & ~3);
    const float rz0 = 1.0f / z0;
    const float rz1 = 1.0f / z1;

    const int r0 = wid * 16 + g;
    float* const ob = out + (size_t)(i0 + r0) * HD + (head << 6) + t2;
#pragma unroll
    for (int nb = 0; nb < 8; ++nb) {
        *(float2*)(ob + nb * 8)          = make_float2(acc[nb][0] * rz0, acc[nb][1] * rz0);
        *(float2*)(ob + nb * 8 + 8 * HD) = make_float2(acc[nb][2] * rz1, acc[nb][3] * rz1);
    }
}

extern "C" void kernel_launch(void* const* d_in, const int* in_sizes, int n_in,
                              void* d_out, int out_size) {
    const float* x   = (const float*)d_in[0];
    const int*   adj = (const int*)  d_in[1];
    const float* W   = (const float*)d_in[2];
    const float* a1  = (const float*)d_in[3];
    const float* a2  = (const float*)d_in[4];
    float* out = (float*)d_out;

    cudaFuncSetAttribute(aggregate_mma, cudaFuncAttributeMaxDynamicSharedMemorySize, SM_TOT);

    gemm_xw      <<<dim3(HD / 64, NN / 64), 256>>>(x, W);
    scores       <<<(NN * H / 2) / 256, 256>>>(a1, a2);
    pack_adj     <<<NN * NN / 128 / 8, 256>>>(adj);
    aggregate_mma<<<(NN / 64) * H, 128, SM_TOT>>>(out);
}

// round 12
// speedup vs baseline: 5.2481x; 1.0884x over previous
#include <cuda_runtime.h>
#include <cuda_fp16.h>
#include <cstdint>

#define NN   4096
#define INF  256
#define HD   256   // H*D
#define H    4
#define D    64

// ---------------- device scratch (no cudaMalloc allowed) ----------------
__device__ float4   g_fi [H * NN];                   // (si, e^si, e^.2si, 0) fp32
__device__ __align__(16) uint4  g_fjp[H * NN / 2];   // per (h, j-pair): {sj2, e^sj2, e^.2sj2, 0}
__device__ __align__(16) __half g_ht [H * D * NN];   // h transposed per head: [h][f][j]
__device__ __align__(16) uint32_t g_adjb[NN * NN / 32];  // packed adjacency bits

// ---------------- smem layout for aggregate_mma (bytes) ----------------
#define PSB    272                    // padded B/A row stride (136 halfs)
#define BBUF   17408                  // one B buffer: 64 rows x 272
#define SM_FJP 0                      // 2 x uint4[64] = 2048
#define SM_AS  2048                   // A: 64 x 272 = 17408
#define SM_BS  19456                  // 2 x 17408 = 34816
#define SM_TOT 54272

__device__ __forceinline__ uint32_t smem_u32(const void* p) {
    uint32_t a;
    asm("{ .reg .u64 t; cvta.to.shared.u64 t, %1; cvt.u32.u64 %0, t; }"
        : "=r"(a) : "l"(p));
    return a;
}

__device__ __forceinline__ void cpa16(uint32_t dst, const void* src) {
    asm volatile("cp.async.cg.shared.global [%0], [%1], 16;" :: "r"(dst), "l"(src));
}

__device__ __forceinline__ void mma16816(float* c,
                                         uint32_t a0, uint32_t a1, uint32_t a2, uint32_t a3,
                                         uint32_t b0, uint32_t b1) {
    asm volatile(
        "mma.sync.aligned.m16n8k16.row.col.f32.f16.f16.f32 "
        "{%0,%1,%2,%3}, {%4,%5,%6,%7}, {%8,%9}, {%0,%1,%2,%3};"
        : "+f"(c[0]), "+f"(c[1]), "+f"(c[2]), "+f"(c[3])
        : "r"(a0), "r"(a1), "r"(a2), "r"(a3), "r"(b0), "r"(b1));
}

__device__ __forceinline__ void ldsm4(uint32_t& r0, uint32_t& r1, uint32_t& r2, uint32_t& r3,
                                      uint32_t addr) {
    asm volatile("ldmatrix.sync.aligned.m8n8.x4.shared.b16 {%0,%1,%2,%3}, [%4];"
                 : "=r"(r0), "=r"(r1), "=r"(r2), "=r"(r3) : "r"(addr));
}

__device__ __forceinline__ __half2 h2bits(uint32_t v) { return *(__half2*)&v; }
__device__ __forceinline__ uint32_t bitsh2(__half2 v) { return *(uint32_t*)&v; }

// 2 masked weights from 2 adjacency bits (bb)
__device__ __forceinline__ uint32_t wcalc(uint4 q, uint32_t bb,
                                          __half2 negsi2, __half2 epi2, __half2 eni2) {
    __half2 cond = __hgt2(h2bits(q.x), negsi2);
    __half2 ph   = __hmul2(epi2, h2bits(q.y));
    __half2 pl   = __hmul2(eni2, h2bits(q.z));
    __half2 w    = __hfma2(cond, __hsub2(ph, pl), pl);
    uint32_t mb  = (bb & 1u) * 0x3C00u + (bb & 2u) * 0x1E000000u;
    return bitsh2(__hmul2(w, h2bits(mb)));
}

// ---------------- K0: pack adjacency to bits ----------------
__global__ __launch_bounds__(256) void pack_adj(const int* __restrict__ adj) {
    const int w    = (blockIdx.x * blockDim.x + threadIdx.x) >> 5;
    const int lane = threadIdx.x & 31;
    const size_t base = (size_t)w << 7;
    int v0 = __ldg(adj + base + lane);
    int v1 = __ldg(adj + base + 32 + lane);
    int v2 = __ldg(adj + base + 64 + lane);
    int v3 = __ldg(adj + base + 96 + lane);
    uint32_t b0 = __ballot_sync(0xffffffffu, v0 > 0);
    uint32_t b1 = __ballot_sync(0xffffffffu, v1 > 0);
    uint32_t b2 = __ballot_sync(0xffffffffu, v2 > 0);
    uint32_t b3 = __ballot_sync(0xffffffffu, v3 > 0);
    if (lane == 0)
        *(uint4*)&g_adjb[base >> 5] = make_uint4(b0, b1, b2, b3);
}

// ---------------- K1: h = x @ W, fused fp16 transpose + scores epilogue ----------------
__global__ __launch_bounds__(256) void gemm_xw(const float* __restrict__ x,
                                               const float* __restrict__ W,
                                               const float* __restrict__ a1,
                                               const float* __restrict__ a2) {
    __shared__ float As[16][65];
    __shared__ float Bs[16][64];
    __shared__ __half Ts[64][80];
    const int t  = threadIdx.x;
    const int tx = t & 15, ty = t >> 4;
    const int m0 = blockIdx.y * 64;
    const int head = blockIdx.x;
    const int n0 = head * 64;

    float acc[4][4];
#pragma unroll
    for (int i = 0; i < 4; i++)
#pragma unroll
        for (int j = 0; j < 4; j++) acc[i][j] = 0.f;

    for (int k0 = 0; k0 < INF; k0 += 16) {
        {
            int m  = t >> 2;
            int kq = (t & 3) << 2;
            float4 v = *(const float4*)&x[(m0 + m) * INF + k0 + kq];
            As[kq + 0][m] = v.x; As[kq + 1][m] = v.y;
            As[kq + 2][m] = v.z; As[kq + 3][m] = v.w;
        }
#pragma unroll
        for (int r = 0; r < 4; r++) {
            int k = (t >> 6) + (r << 2);
            int n = t & 63;
            Bs[k][n] = W[(k0 + k) * HD + n0 + n];
        }
        __syncthreads();
#pragma unroll
        for (int k = 0; k < 16; k++) {
            float a[4], b[4];
#pragma unroll
            for (int i = 0; i < 4; i++) a[i] = As[k][ty * 4 + i];
#pragma unroll
            for (int j = 0; j < 4; j++) b[j] = Bs[k][tx * 4 + j];
#pragma unroll
            for (int i = 0; i < 4; i++)
#pragma unroll
                for (int j = 0; j < 4; j++) acc[i][j] += a[i] * b[j];
        }
        __syncthreads();
    }

    // fp16 transpose bounce for g_ht
#pragma unroll
    for (int i = 0; i < 4; i++)
#pragma unroll
        for (int j = 0; j < 4; j++)
            Ts[tx * 4 + j][ty * 4 + i] = __float2half(acc[i][j]);

    // fused scores: si/sj dots for this block's 64 nodes x this head
    {
        float a1v[4], a2v[4];
#pragma unroll
        for (int j = 0; j < 4; j++) {
            a1v[j] = __ldg(a1 + tx * 4 + j);
            a2v[j] = __ldg(a2 + tx * 4 + j);
        }
        float s1[4], s2[4];
#pragma unroll
        for (int i = 0; i < 4; i++) {
            s1[i] = acc[i][0] * a1v[0] + acc[i][1] * a1v[1]
                  + acc[i][2] * a1v[2] + acc[i][3] * a1v[3];
            s2[i] = acc[i][0] * a2v[0] + acc[i][1] * a2v[1]
                  + acc[i][2] * a2v[2] + acc[i][3] * a2v[3];
        }
#pragma unroll
        for (int m = 1; m < 16; m <<= 1)
#pragma unroll
            for (int i = 0; i < 4; i++) {
                s1[i] += __shfl_xor_sync(0xffffffffu, s1[i], m);
                s2[i] += __shfl_xor_sync(0xffffffffu, s2[i], m);
            }
        if (tx == 0) {
            const int nb = m0 + ty * 4;
#pragma unroll
            for (int i = 0; i < 4; i++)
                g_fi[head * NN + nb + i] =
                    make_float4(s1[i], __expf(s1[i]), __expf(0.2f * s1[i]), 0.f);
#pragma unroll
            for (int p = 0; p < 2; p++) {
                uint4 o;
                o.x = bitsh2(__floats2half2_rn(s2[2 * p], s2[2 * p + 1]));
                o.y = bitsh2(__floats2half2_rn(__expf(s2[2 * p]), __expf(s2[2 * p + 1])));
                o.z = bitsh2(__floats2half2_rn(__expf(0.2f * s2[2 * p]),
                                               __expf(0.2f * s2[2 * p + 1])));
                o.w = 0;
                g_fjp[head * (NN / 2) + (nb >> 1) + p] = o;
            }
        }
    }
    __syncthreads();
#pragma unroll
    for (int r = 0; r < 2; ++r) {
        int id = t + (r << 8);
        int f  = id >> 3, u = id & 7;
        uint4 v = *(const uint4*)&Ts[f][u * 8];
        *(uint4*)(g_ht + (((size_t)(head * 64 + f)) << 12) + m0 + u * 8) = v;
    }
}

// ---------------- K3: pipelined HMMA masked-softmax aggregation ----------------
// CTA = (64 i-rows, head), 128 threads / 4 warps, 4 CTAs/SM. Double-buffered cp.async
// tiles, adjacency bits in registers, Z via constant ones-column fragment.
__global__ __launch_bounds__(128, 4) void aggregate_mma(float* __restrict__ out) {
    extern __shared__ char sm[];
    uint4* fjp = (uint4*)(sm + SM_FJP);
    char*  Ab  = sm + SM_AS;

    const int t    = threadIdx.x;
    const int lane = t & 31, wid = t >> 5;
    const int head = blockIdx.x & 3;
    const int i0   = (blockIdx.x >> 2) << 6;

    const uint32_t sm_u  = smem_u32(sm);
    const uint32_t fjp_u = sm_u + SM_FJP;
    const uint32_t Ab_u  = sm_u + SM_AS;
    const uint32_t Bb_u  = sm_u + SM_BS;

    // gen identity: row il, j-half jh
    const int il = t >> 1;
    const int jh = (t & 1) << 6;
    const float4 fi = __ldg(&g_fi[head * NN + i0 + il]);
    const __half2 negsi2 = __float2half2_rn(-fi.x);
    const __half2 epi2   = __float2half2_rn(fi.y);
    const __half2 eni2   = __float2half2_rn(fi.z);
    char* const agen = Ab + il * PSB + (jh << 1);
    const uint32_t* __restrict__ arow = g_adjb + ((size_t)(i0 + il) << 7) + (jh >> 5);

    auto stage = [&](int cc) {
        const int j0  = cc << 7;
        const int buf = cc & 1;
        if (t < 64)
            cpa16(fjp_u + buf * 1024 + t * 16,
                  (const char*)(g_fjp + head * (NN / 2) + (j0 >> 1) + t));
#pragma unroll
        for (int r = 0; r < 8; ++r) {
            int id = t + (r << 7);
            int f  = id >> 4, u = id & 15;
            cpa16(Bb_u + buf * BBUF + f * PSB + (u << 4),
                  g_ht + (((size_t)(head * D + f)) << 12) + j0 + u * 8);
        }
    };

    stage(0);
    asm volatile("cp.async.commit_group;");
    uint32_t aw0 = __ldg(arow + 0);
    uint32_t aw1 = __ldg(arow + 1);

    // mma identity
    const int g  = lane >> 2;
    const int t2 = (lane & 3) << 1;
    const uint32_t lrow = ((lane >> 3) & 1) * 8 + (lane & 7);
    const uint32_t lcol = (lane >> 4) * 16;
    const uint32_t a_base = Ab_u + (wid * 16 + lrow) * PSB + lcol;
    const uint32_t zfrag  = (lane < 4) ? 0x3C003C00u : 0u;  // ones-column B fragment

    float acc[8][4];
    float accz[4];
#pragma unroll
    for (int nb = 0; nb < 8; nb++)
#pragma unroll
        for (int q = 0; q < 4; q++) acc[nb][q] = 0.f;
#pragma unroll
    for (int q = 0; q < 4; q++) accz[q] = 0.f;

    for (int c = 0; c < 32; ++c) {
        const int buf = c & 1;
        asm volatile("cp.async.wait_group 0;" ::: "memory");   // chunk c landed
        __syncthreads();   // all warps past mma(c-1) -> buffer (c+1)&1 free; tiles visible

        if (c + 1 < 32) {
            stage(c + 1);
            asm volatile("cp.async.commit_group;");
        }

        // ---- generate A tile (64 masked weights / thread) ----
        {
            const uint4* fq = fjp + buf * 64 + (jh >> 1);
#pragma unroll
            for (int gg = 0; gg < 8; ++gg) {
                uint4 q0 = fq[gg * 4 + 0];
                uint4 q1 = fq[gg * 4 + 1];
                uint4 q2 = fq[gg * 4 + 2];
                uint4 q3 = fq[gg * 4 + 3];
                const uint32_t ws = (gg < 4) ? aw0 : aw1;
                const int sh = (gg & 3) << 3;
                uint4 pk;
                pk.x = wcalc(q0, (ws >> (sh + 0)) & 3u, negsi2, epi2, eni2);
                pk.y = wcalc(q1, (ws >> (sh + 2)) & 3u, negsi2, epi2, eni2);
                pk.z = wcalc(q2, (ws >> (sh + 4)) & 3u, negsi2, epi2, eni2);
                pk.w = wcalc(q3, (ws >> (sh + 6)) & 3u, negsi2, epi2, eni2);
                *(uint4*)(agen + (gg << 4)) = pk;
            }
        }
        // prefetch adjacency words for chunk c+1 (hidden behind MMA)
        uint32_t awn0 = 0, awn1 = 0;
        if (c < 31) {
            awn0 = __ldg(arow + ((c + 1) << 2));
            awn1 = __ldg(arow + ((c + 1) << 2) + 1);
        }
        __syncthreads();

        // ---- HMMA: 8 k-steps, 8 n-blocks + constant Z column ----
        const uint32_t Bu = Bb_u + buf * BBUF;
        const uint32_t b_base0 = Bu + (lrow +  0) * PSB + lcol;
        const uint32_t b_base1 = Bu + (lrow + 16) * PSB + lcol;
        const uint32_t b_base2 = Bu + (lrow + 32) * PSB + lcol;
        const uint32_t b_base3 = Bu + (lrow + 48) * PSB + lcol;
#pragma unroll
        for (int ks = 0; ks < 8; ++ks) {
            const uint32_t ko = ks * 32;
            uint32_t a0, a1, a2, a3, b0, b1, b2, b3;
            ldsm4(a0, a1, a2, a3, a_base + ko);
            ldsm4(b0, b1, b2, b3, b_base0 + ko);
            mma16816(acc[0], a0, a1, a2, a3, b0, b2);
            mma16816(acc[1], a0, a1, a2, a3, b1, b3);
            ldsm4(b0, b1, b2, b3, b_base1 + ko);
            mma16816(acc[2], a0, a1, a2, a3, b0, b2);
            mma16816(acc[3], a0, a1, a2, a3, b1, b3);
            ldsm4(b0, b1, b2, b3, b_base2 + ko);
            mma16816(acc[4], a0, a1, a2, a3, b0, b2);
            mma16816(acc[5], a0, a1, a2, a3, b1, b3);
            ldsm4(b0, b1, b2, b3, b_base3 + ko);
            mma16816(acc[6], a0, a1, a2, a3, b0, b2);
            mma16816(acc[7], a0, a1, a2, a3, b1, b3);
            mma16816(accz, a0, a1, a2, a3, zfrag, zfrag);
        }
        aw0 = awn0; aw1 = awn1;
    }

    // Z from column n=64 (fragment col 0 -> lanes with lane%4==0)
    const float z0 = __shfl_sync(0xffffffffu, accz[0], lane & ~3);
    const float z1 = __shfl_sync(0xffffffffu, accz[2], lane & ~3);
    const float rz0 = 1.0f / z0;
    const float rz1 = 1.0f / z1;

    const int r0 = wid * 16 + g;
    float* const ob = out + (size_t)(i0 + r0) * HD + (head << 6) + t2;
#pragma unroll
    for (int nb = 0; nb < 8; ++nb) {
        *(float2*)(ob + nb * 8)          = make_float2(acc[nb][0] * rz0, acc[nb][1] * rz0);
        *(float2*)(ob + nb * 8 + 8 * HD) = make_float2(acc[nb][2] * rz1, acc[nb][3] * rz1);
    }
}

extern "C" void kernel_launch(void* const* d_in, const int* in_sizes, int n_in,
                              void* d_out, int out_size) {
    const float* x   = (const float*)d_in[0];
    const int*   adj = (const int*)  d_in[1];
    const float* W   = (const float*)d_in[2];
    const float* a1  = (const float*)d_in[3];
    const float* a2  = (const float*)d_in[4];
    float* out = (float*)d_out;

    cudaFuncSetAttribute(aggregate_mma, cudaFuncAttributeMaxDynamicSharedMemorySize, SM_TOT);

    gemm_xw      <<<dim3(H, NN / 64), 256>>>(x, W, a1, a2);
    pack_adj     <<<NN * NN / 128 / 8, 256>>>(adj);
    aggregate_mma<<<(NN / 64) * H, 128, SM_TOT>>>(out);
}

// round 13
// speedup vs baseline: 7.0736x; 1.3478x over previous
#include <cuda_runtime.h>
#include <cuda_fp16.h>
#include <cstdint>

#define NN   4096
#define INF  256
#define HD   256   // H*D
#define H    4
#define D    64

// ---------------- device scratch (no cudaMalloc allowed) ----------------
__device__ float4   g_fi [H * NN];                   // (si, e^si, e^.2si, 0) fp32
__device__ __align__(16) uint4  g_fjp[H * NN / 2];   // per (h, j-pair): {sj2, e^sj2, e^.2sj2, 0}
__device__ __align__(16) __half g_ht [H * D * NN];   // h transposed per head: [h][f][j]
__device__ __align__(16) uint32_t g_adjb[NN * NN / 32];  // packed adjacency bits
__device__ __align__(16) __half g_xh [NN * INF];     // x in fp16
__device__ __align__(16) __half g_wh [HD * INF];     // W^T in fp16: [n][k]

// ---------------- smem layouts ----------------
#define PSB    272                    // aggregate B row stride (136 halfs)
#define BBUF   17408                  // one B buffer: 64 rows x 272
#define SM_FJP 0                      // 2 x uint4[64] = 2048
#define SM_BS  2048                   // 2 x 17408
#define SM_TOT 36864

#define PSG    144                    // gemm tile row stride (72 halfs)
#define GA0    0                      // A bufs: 128 x 144 = 18432 each
#define GA1    18432
#define GB0    36864                  // B bufs: 64 x 144 = 9216 each
#define GB1    46080
#define GSB    55296                  // score float2[128] = 1024
#define GTOT   56320
// Ts (transpose bounce, 64 x 272 = 17408) aliases GA0 after last A0 use.

__device__ __forceinline__ uint32_t smem_u32(const void* p) {
    uint32_t a;
    asm("{ .reg .u64 t; cvta.to.shared.u64 t, %1; cvt.u32.u64 %0, t; }"
        : "=r"(a) : "l"(p));
    return a;
}

__device__ __forceinline__ void cpa16(uint32_t dst, const void* src) {
    asm volatile("cp.async.cg.shared.global [%0], [%1], 16;" :: "r"(dst), "l"(src));
}

__device__ __forceinline__ void mma16816(float* c,
                                         uint32_t a0, uint32_t a1, uint32_t a2, uint32_t a3,
                                         uint32_t b0, uint32_t b1) {
    asm volatile(
        "mma.sync.aligned.m16n8k16.row.col.f32.f16.f16.f32 "
        "{%0,%1,%2,%3}, {%4,%5,%6,%7}, {%8,%9}, {%0,%1,%2,%3};"
        : "+f"(c[0]), "+f"(c[1]), "+f"(c[2]), "+f"(c[3])
        : "r"(a0), "r"(a1), "r"(a2), "r"(a3), "r"(b0), "r"(b1));
}

__device__ __forceinline__ void ldsm4(uint32_t& r0, uint32_t& r1, uint32_t& r2, uint32_t& r3,
                                      uint32_t addr) {
    asm volatile("ldmatrix.sync.aligned.m8n8.x4.shared.b16 {%0,%1,%2,%3}, [%4];"
                 : "=r"(r0), "=r"(r1), "=r"(r2), "=r"(r3) : "r"(addr));
}

__device__ __forceinline__ __half2 h2bits(uint32_t v) { return *(__half2*)&v; }
__device__ __forceinline__ uint32_t bitsh2(__half2 v) { return *(uint32_t*)&v; }

// 2 masked weights from 2 adjacency bits (bb)
__device__ __forceinline__ uint32_t wcalc(uint4 q, uint32_t bb,
                                          __half2 negsi2, __half2 epi2, __half2 eni2) {
    __half2 cond = __hgt2(h2bits(q.x), negsi2);
    __half2 ph   = __hmul2(epi2, h2bits(q.y));
    __half2 pl   = __hmul2(eni2, h2bits(q.z));
    __half2 w    = __hfma2(cond, __hsub2(ph, pl), pl);
    uint32_t mb  = (bb & 1u) * 0x3C00u + (bb & 2u) * 0x1E000000u;
    return bitsh2(__hmul2(w, h2bits(mb)));
}

// ---------------- K_cvt: fp16 copies of x and W^T ----------------
__global__ __launch_bounds__(256) void cvt_inputs(const float* __restrict__ x,
                                                  const float* __restrict__ W) {
    const int b = blockIdx.x, t = threadIdx.x;
    if (b < 1024) {                    // x: 1M elems, 4 per thread
        int id = (b << 8) + t;
        float4 v = *(const float4*)(x + (size_t)id * 4);
        uint2 o;
        o.x = bitsh2(__floats2half2_rn(v.x, v.y));
        o.y = bitsh2(__floats2half2_rn(v.z, v.w));
        *(uint2*)(g_xh + (size_t)id * 4) = o;
    } else {                           // W^T: 64K elems, 1 per thread
        int id = ((b - 1024) << 8) + t;
        int n = id >> 8, k = id & 255;
        g_wh[(size_t)n * INF + k] = __float2half(__ldg(W + (size_t)k * HD + n));
    }
}

// ---------------- K0: pack adjacency to bits ----------------
__global__ __launch_bounds__(256) void pack_adj(const int* __restrict__ adj) {
    const int w    = (blockIdx.x * blockDim.x + threadIdx.x) >> 5;
    const int lane = threadIdx.x & 31;
    const size_t base = (size_t)w << 7;
    int v0 = __ldg(adj + base + lane);
    int v1 = __ldg(adj + base + 32 + lane);
    int v2 = __ldg(adj + base + 64 + lane);
    int v3 = __ldg(adj + base + 96 + lane);
    uint32_t b0 = __ballot_sync(0xffffffffu, v0 > 0);
    uint32_t b1 = __ballot_sync(0xffffffffu, v1 > 0);
    uint32_t b2 = __ballot_sync(0xffffffffu, v2 > 0);
    uint32_t b3 = __ballot_sync(0xffffffffu, v3 > 0);
    if (lane == 0)
        *(uint4*)&g_adjb[base >> 5] = make_uint4(b0, b1, b2, b3);
}

// ---------------- K1: HMMA h = x @ W + scores + fp16 transpose ----------------
// CTA = (128 m-rows, head). 8 warps; warp w: rows 16w..16w+16, n = 64 head cols.
__global__ __launch_bounds__(256, 1) void gemm_hmma(const float* __restrict__ a1,
                                                    const float* __restrict__ a2,
                                                    float* __restrict__ outdummy) {
    extern __shared__ char sm[];
    const uint32_t sm_u = smem_u32(sm);
    const int t    = threadIdx.x;
    const int lane = t & 31, wid = t >> 5;
    const int head = blockIdx.x & 3;
    const int m0   = (blockIdx.x >> 2) << 7;

    auto stageA = [&](int kc) {
        const uint32_t Au = sm_u + ((kc & 1) ? GA1 : GA0);
#pragma unroll
        for (int r = 0; r < 4; ++r) {
            int id  = t + (r << 8);
            int row = id >> 3, u = id & 7;
            cpa16(Au + row * PSG + (u << 4),
                  g_xh + (size_t)(m0 + row) * INF + (kc << 6) + (u << 3));
        }
    };
    auto stageB = [&](int kc) {
        const uint32_t Bu = sm_u + ((kc & 1) ? GB1 : GB0);
#pragma unroll
        for (int r = 0; r < 2; ++r) {
            int id  = t + (r << 8);
            int row = id >> 3, u = id & 7;
            cpa16(Bu + row * PSG + (u << 4),
                  g_wh + (size_t)((head << 6) + row) * INF + (kc << 6) + (u << 3));
        }
    };

    stageA(0); stageB(0);
    asm volatile("cp.async.commit_group;");

    const int g  = lane >> 2;
    const int t2 = (lane & 3) << 1;
    const uint32_t lrow = ((lane >> 3) & 1) * 8 + (lane & 7);
    const uint32_t lcol = (lane >> 4) * 16;

    float acc[8][4];
#pragma unroll
    for (int nb = 0; nb < 8; nb++)
#pragma unroll
        for (int q = 0; q < 4; q++) acc[nb][q] = 0.f;

    for (int kc = 0; kc < 4; ++kc) {
        asm volatile("cp.async.wait_group 0;" ::: "memory");
        __syncthreads();
        if (kc < 3) {
            stageA(kc + 1); stageB(kc + 1);
            asm volatile("cp.async.commit_group;");
        }
        const uint32_t Au = sm_u + ((kc & 1) ? GA1 : GA0);
        const uint32_t Bu = sm_u + ((kc & 1) ? GB1 : GB0);
        const uint32_t a_base  = Au + (wid * 16 + lrow) * PSG + lcol;
        const uint32_t b_base0 = Bu + (lrow +  0) * PSG + lcol;
        const uint32_t b_base1 = Bu + (lrow + 16) * PSG + lcol;
        const uint32_t b_base2 = Bu + (lrow + 32) * PSG + lcol;
        const uint32_t b_base3 = Bu + (lrow + 48) * PSG + lcol;
#pragma unroll
        for (int ks = 0; ks < 4; ++ks) {
            const uint32_t ko = ks * 32;
            uint32_t a0, a1r, a2r, a3, b0, b1, b2, b3;
            ldsm4(a0, a1r, a2r, a3, a_base + ko);
            ldsm4(b0, b1, b2, b3, b_base0 + ko);
            mma16816(acc[0], a0, a1r, a2r, a3, b0, b2);
            mma16816(acc[1], a0, a1r, a2r, a3, b1, b3);
            ldsm4(b0, b1, b2, b3, b_base1 + ko);
            mma16816(acc[2], a0, a1r, a2r, a3, b0, b2);
            mma16816(acc[3], a0, a1r, a2r, a3, b1, b3);
            ldsm4(b0, b1, b2, b3, b_base2 + ko);
            mma16816(acc[4], a0, a1r, a2r, a3, b0, b2);
            mma16816(acc[5], a0, a1r, a2r, a3, b1, b3);
            ldsm4(b0, b1, b2, b3, b_base3 + ko);
            mma16816(acc[6], a0, a1r, a2r, a3, b0, b2);
            mma16816(acc[7], a0, a1r, a2r, a3, b1, b3);
        }
    }

    // ---- scores from fragments ----
    float s1r0 = 0.f, s1r1 = 0.f, s2r0 = 0.f, s2r1 = 0.f;
#pragma unroll
    for (int nb = 0; nb < 8; ++nb) {
        const int c0 = (nb << 3) + t2;
        float a1a = __ldg(a1 + c0), a1b = __ldg(a1 + c0 + 1);
        float a2a = __ldg(a2 + c0), a2b = __ldg(a2 + c0 + 1);
        s1r0 += acc[nb][0] * a1a + acc[nb][1] * a1b;
        s2r0 += acc[nb][0] * a2a + acc[nb][1] * a2b;
        s1r1 += acc[nb][2] * a1a + acc[nb][3] * a1b;
        s2r1 += acc[nb][2] * a2a + acc[nb][3] * a2b;
    }
#pragma unroll
    for (int m = 1; m < 4; m <<= 1) {
        s1r0 += __shfl_xor_sync(0xffffffffu, s1r0, m);
        s2r0 += __shfl_xor_sync(0xffffffffu, s2r0, m);
        s1r1 += __shfl_xor_sync(0xffffffffu, s1r1, m);
        s2r1 += __shfl_xor_sync(0xffffffffu, s2r1, m);
    }

    __syncthreads();   // all MMA reads done; GA0 region reusable as Ts
    __half* Ts = (__half*)(sm);        // [64 cols][136 rows-stride]
    float2* sb = (float2*)(sm + GSB);
    if ((lane & 3) == 0) {
        const int r = wid * 16 + g;
        sb[r]     = make_float2(s1r0, s2r0);
        sb[r + 8] = make_float2(s1r1, s2r1);
    }
    {
        const int r = wid * 16 + g;
#pragma unroll
        for (int nb = 0; nb < 8; ++nb) {
            const int c0 = (nb << 3) + t2;
            Ts[c0 * 136 + r]           = __float2half(acc[nb][0]);
            Ts[(c0 + 1) * 136 + r]     = __float2half(acc[nb][1]);
            Ts[c0 * 136 + r + 8]       = __float2half(acc[nb][2]);
            Ts[(c0 + 1) * 136 + r + 8] = __float2half(acc[nb][3]);
        }
    }
    __syncthreads();

    if (t < 128) {                     // g_fi
        float2 s = sb[t];
        g_fi[head * NN + m0 + t] =
            make_float4(s.x, __expf(s.x), __expf(0.2f * s.x), 0.f);
    } else if (t < 192) {              // g_fjp pairs
        const int p = t - 128;
        float2 sa = sb[2 * p], sbv = sb[2 * p + 1];
        uint4 o;
        o.x = bitsh2(__floats2half2_rn(sa.y, sbv.y));
        o.y = bitsh2(__floats2half2_rn(__expf(sa.y), __expf(sbv.y)));
        o.z = bitsh2(__floats2half2_rn(__expf(0.2f * sa.y), __expf(0.2f * sbv.y)));
        o.w = 0;
        g_fjp[head * (NN / 2) + (m0 >> 1) + p] = o;
    }
    // g_ht store: [f][m0..m0+128)
#pragma unroll
    for (int r = 0; r < 4; ++r) {
        int id = t + (r << 8);
        int f  = id >> 4, u = id & 15;
        uint4 v = *(const uint4*)(sm + f * PSB + (u << 4));
        *(uint4*)(g_ht + (((size_t)((head << 6) + f)) << 12) + m0 + (u << 3)) = v;
    }
}

// ---------------- K3: pipelined HMMA aggregation, A fragments in registers ----------------
__global__ __launch_bounds__(128, 4) void aggregate_mma(float* __restrict__ out) {
    extern __shared__ char sm[];
    const int t    = threadIdx.x;
    const int lane = t & 31, wid = t >> 5;
    const int head = blockIdx.x & 3;
    const int i0   = (blockIdx.x >> 2) << 6;

    const uint32_t sm_u  = smem_u32(sm);
    const uint32_t fjp_u = sm_u + SM_FJP;
    const uint32_t Bb_u  = sm_u + SM_BS;

    const int g   = lane >> 2;
    const int c2q = lane & 3;
    const int t2  = c2q << 1;

    // row constants for the 2 fragment rows this lane generates
    const int rA = i0 + wid * 16 + g;
    const float4 fiA = __ldg(&g_fi[head * NN + rA]);
    const float4 fiB = __ldg(&g_fi[head * NN + rA + 8]);
    const __half2 negA = __float2half2_rn(-fiA.x), epA = __float2half2_rn(fiA.y),
                  enA  = __float2half2_rn(fiA.z);
    const __half2 negB = __float2half2_rn(-fiB.x), epB = __float2half2_rn(fiB.y),
                  enB  = __float2half2_rn(fiB.z);
    const uint32_t* __restrict__ adjA = g_adjb + ((size_t)rA << 7);
    const uint32_t* __restrict__ adjB = g_adjb + ((size_t)(rA + 8) << 7);

    auto stage = [&](int cc) {
        const int j0  = cc << 7;
        const int buf = cc & 1;
        if (t < 64)
            cpa16(fjp_u + buf * 1024 + t * 16,
                  (const char*)(g_fjp + head * (NN / 2) + (j0 >> 1) + t));
#pragma unroll
        for (int r = 0; r < 8; ++r) {
            int id = t + (r << 7);
            int f  = id >> 4, u = id & 15;
            cpa16(Bb_u + buf * BBUF + f * PSB + (u << 4),
                  g_ht + (((size_t)((head << 6) + f)) << 12) + j0 + (u << 3));
        }
    };

    stage(0);
    asm volatile("cp.async.commit_group;");
    uint32_t awA[4], awB[4];
#pragma unroll
    for (int q = 0; q < 4; ++q) { awA[q] = __ldg(adjA + q); awB[q] = __ldg(adjB + q); }

    const uint32_t lrow = ((lane >> 3) & 1) * 8 + (lane & 7);
    const uint32_t lcol = (lane >> 4) * 16;
    const uint32_t zfrag = (lane < 4) ? 0x3C003C00u : 0u;

    float acc[8][4];
    float accz[4];
#pragma unroll
    for (int nb = 0; nb < 8; nb++)
#pragma unroll
        for (int q = 0; q < 4; q++) acc[nb][q] = 0.f;
#pragma unroll
    for (int q = 0; q < 4; q++) accz[q] = 0.f;

    for (int c = 0; c < 32; ++c) {
        const int buf = c & 1;
        asm volatile("cp.async.wait_group 0;" ::: "memory");
        __syncthreads();
        if (c + 1 < 32) {
            stage(c + 1);
            asm volatile("cp.async.commit_group;");
        }
        // prefetch adjacency words for next chunk (hidden behind MMA)
        uint32_t nxA[4], nxB[4];
        if (c + 1 < 32) {
            const int o = (c + 1) << 2;
#pragma unroll
            for (int q = 0; q < 4; ++q) {
                nxA[q] = __ldg(adjA + o + q);
                nxB[q] = __ldg(adjB + o + q);
            }
        }

        const uint32_t Bu = Bb_u + buf * BBUF;
        const uint32_t b_base0 = Bu + (lrow +  0) * PSB + lcol;
        const uint32_t b_base1 = Bu + (lrow + 16) * PSB + lcol;
        const uint32_t b_base2 = Bu + (lrow + 32) * PSB + lcol;
        const uint32_t b_base3 = Bu + (lrow + 48) * PSB + lcol;
        const uint32_t fq = fjp_u + buf * 1024 + c2q * 16;

#pragma unroll
        for (int ks = 0; ks < 8; ++ks) {
            // A fragments generated in-register (rows g, g+8; j-pairs of this lane)
            uint4 qa = *(const uint4*)(uintptr_t)0;  // placeholder (replaced below)
            // (real loads via inline asm to keep shared-space addressing)
            uint32_t qax, qay, qaz, qaw, qbx, qby, qbz, qbw;
            asm volatile("ld.shared.v4.b32 {%0,%1,%2,%3}, [%4];"
                         : "=r"(qax), "=r"(qay), "=r"(qaz), "=r"(qaw)
                         : "r"(fq + ks * 128));
            asm volatile("ld.shared.v4.b32 {%0,%1,%2,%3}, [%4];"
                         : "=r"(qbx), "=r"(qby), "=r"(qbz), "=r"(qbw)
                         : "r"(fq + ks * 128 + 64));
            (void)qa;
            const uint4 qav = make_uint4(qax, qay, qaz, qaw);
            const uint4 qbv = make_uint4(qbx, qby, qbz, qbw);
            const int pos = ((ks & 1) << 4) + t2;
            const uint32_t wA = awA[ks >> 1], wB = awB[ks >> 1];
            uint32_t a0 = wcalc(qav, (wA >> pos) & 3u,       negA, epA, enA);
            uint32_t a1 = wcalc(qav, (wB >> pos) & 3u,       negB, epB, enB);
            uint32_t a2 = wcalc(qbv, (wA >> (pos + 8)) & 3u, negA, epA, enA);
            uint32_t a3 = wcalc(qbv, (wB >> (pos + 8)) & 3u, negB, epB, enB);

            const uint32_t ko = ks * 32;
            uint32_t b0, b1, b2, b3;
            ldsm4(b0, b1, b2, b3, b_base0 + ko);
            mma16816(acc[0], a0, a1, a2, a3, b0, b2);
            mma16816(acc[1], a0, a1, a2, a3, b1, b3);
            ldsm4(b0, b1, b2, b3, b_base1 + ko);
            mma16816(acc[2], a0, a1, a2, a3, b0, b2);
            mma16816(acc[3], a0, a1, a2, a3, b1, b3);
            ldsm4(b0, b1, b2, b3, b_base2 + ko);
            mma16816(acc[4], a0, a1, a2, a3, b0, b2);
            mma16816(acc[5], a0, a1, a2, a3, b1, b3);
            ldsm4(b0, b1, b2, b3, b_base3 + ko);
            mma16816(acc[6], a0, a1, a2, a3, b0, b2);
            mma16816(acc[7], a0, a1, a2, a3, b1, b3);
            mma16816(accz, a0, a1, a2, a3, zfrag, zfrag);
        }
#pragma unroll
        for (int q = 0; q < 4; ++q) { awA[q] = nxA[q]; awB[q] = nxB[q]; }
    }

    const float z0 = __shfl_sync(0xffffffffu, accz[0], lane & ~3);
    const float z1 = __shfl_sync(0xffffffffu, accz[2], lane & ~3);
    const float rz0 = 1.0f / z0;
    const float rz1 = 1.0f / z1;

    const int r0 = wid * 16 + g;
    float* const ob = out + (size_t)(i0 + r0) * HD + (head << 6) + t2;
#pragma unroll
    for (int nb = 0; nb < 8; ++nb) {
        *(float2*)(ob + nb * 8)          = make_float2(acc[nb][0] * rz0, acc[nb][1] * rz0);
        *(float2*)(ob + nb * 8 + 8 * HD) = make_float2(acc[nb][2] * rz1, acc[nb][3] * rz1);
    }
}

extern "C" void kernel_launch(void* const* d_in, const int* in_sizes, int n_in,
                              void* d_out, int out_size) {
    const float* x   = (const float*)d_in[0];
    const int*   adj = (const int*)  d_in[1];
    const float* W   = (const float*)d_in[2];
    const float* a1  = (const float*)d_in[3];
    const float* a2  = (const float*)d_in[4];
    float* out = (float*)d_out;

    cudaFuncSetAttribute(gemm_hmma,     cudaFuncAttributeMaxDynamicSharedMemorySize, GTOT);
    cudaFuncSetAttribute(aggregate_mma, cudaFuncAttributeMaxDynamicSharedMemorySize, SM_TOT);

    cvt_inputs   <<<1024 + 256, 256>>>(x, W);
    gemm_hmma    <<<(NN / 128) * H, 256, GTOT>>>(a1, a2, out);
    pack_adj     <<<NN * NN / 128 / 8, 256>>>(adj);
    aggregate_mma<<<(NN / 64) * H, 128, SM_TOT>>>(out);
}

// round 14
// speedup vs baseline: 7.2712x; 1.0279x over previous
#include <cuda_runtime.h>
#include <cuda_fp16.h>
#include <cstdint>

#define NN   4096
#define INF  256
#define HD   256   // H*D
#define H    4
#define D    64

// ---------------- device scratch (no cudaMalloc allowed) ----------------
__device__ float4   g_fi [H * NN];                   // (si, e^si, e^.2si, 0) fp32
__device__ __align__(16) uint4  g_fjp[H * NN / 2];   // per (h, j-pair): {sj2, e^sj2, e^.2sj2, 0}
__device__ __align__(16) __half g_ht [H * D * NN];   // h transposed per head: [h][f][j]
__device__ __align__(16) uint32_t g_adjb[NN * NN / 32];  // packed adjacency bits
__device__ __align__(16) __half g_xh [NN * INF];     // x in fp16
__device__ __align__(16) __half g_wh [HD * INF];     // W^T in fp16: [n][k]

// ---------------- smem layouts ----------------
#define PSB    272                    // aggregate B row stride (136 halfs)
#define BBUF   17408                  // one B buffer: 64 rows x 272
#define SM_FJP 0                      // 4 x uint4[64] = 4096
#define SM_BS  4096                   // 4 x 17408 = 69632
#define SM_TOT 73728
#define RED_OFF 4096                  // combine scratch aliases B buffers post-loop

#define PSG    144                    // gemm tile row stride (72 halfs)
#define GA0    0
#define GA1    18432
#define GB0    36864
#define GB1    46080
#define GSB    55296
#define GTOT   56320

__device__ __forceinline__ uint32_t smem_u32(const void* p) {
    uint32_t a;
    asm("{ .reg .u64 t; cvta.to.shared.u64 t, %1; cvt.u32.u64 %0, t; }"
        : "=r"(a) : "l"(p));
    return a;
}

__device__ __forceinline__ void cpa16(uint32_t dst, const void* src) {
    asm volatile("cp.async.cg.shared.global [%0], [%1], 16;" :: "r"(dst), "l"(src));
}

__device__ __forceinline__ void mma16816(float* c,
                                         uint32_t a0, uint32_t a1, uint32_t a2, uint32_t a3,
                                         uint32_t b0, uint32_t b1) {
    asm volatile(
        "mma.sync.aligned.m16n8k16.row.col.f32.f16.f16.f32 "
        "{%0,%1,%2,%3}, {%4,%5,%6,%7}, {%8,%9}, {%0,%1,%2,%3};"
        : "+f"(c[0]), "+f"(c[1]), "+f"(c[2]), "+f"(c[3])
        : "r"(a0), "r"(a1), "r"(a2), "r"(a3), "r"(b0), "r"(b1));
}

__device__ __forceinline__ void ldsm4(uint32_t& r0, uint32_t& r1, uint32_t& r2, uint32_t& r3,
                                      uint32_t addr) {
    asm volatile("ldmatrix.sync.aligned.m8n8.x4.shared.b16 {%0,%1,%2,%3}, [%4];"
                 : "=r"(r0), "=r"(r1), "=r"(r2), "=r"(r3) : "r"(addr));
}

__device__ __forceinline__ __half2 h2bits(uint32_t v) { return *(__half2*)&v; }
__device__ __forceinline__ uint32_t bitsh2(__half2 v) { return *(uint32_t*)&v; }

__device__ __forceinline__ uint32_t wcalc(uint4 q, uint32_t bb,
                                          __half2 negsi2, __half2 epi2, __half2 eni2) {
    __half2 cond = __hgt2(h2bits(q.x), negsi2);
    __half2 ph   = __hmul2(epi2, h2bits(q.y));
    __half2 pl   = __hmul2(eni2, h2bits(q.z));
    __half2 w    = __hfma2(cond, __hsub2(ph, pl), pl);
    uint32_t mb  = (bb & 1u) * 0x3C00u + (bb & 2u) * 0x1E000000u;
    return bitsh2(__hmul2(w, h2bits(mb)));
}

// ---------------- K_cvt: fp16 copies of x and W^T ----------------
__global__ __launch_bounds__(256) void cvt_inputs(const float* __restrict__ x,
                                                  const float* __restrict__ W) {
    const int b = blockIdx.x, t = threadIdx.x;
    if (b < 1024) {
        int id = (b << 8) + t;
        float4 v = *(const float4*)(x + (size_t)id * 4);
        uint2 o;
        o.x = bitsh2(__floats2half2_rn(v.x, v.y));
        o.y = bitsh2(__floats2half2_rn(v.z, v.w));
        *(uint2*)(g_xh + (size_t)id * 4) = o;
    } else {
        int id = ((b - 1024) << 8) + t;
        int n = id >> 8, k = id & 255;
        g_wh[(size_t)n * INF + k] = __float2half(__ldg(W + (size_t)k * HD + n));
    }
}

// ---------------- K0: pack adjacency to bits ----------------
__global__ __launch_bounds__(256) void pack_adj(const int* __restrict__ adj) {
    const int w    = (blockIdx.x * blockDim.x + threadIdx.x) >> 5;
    const int lane = threadIdx.x & 31;
    const size_t base = (size_t)w << 7;
    int v0 = __ldg(adj + base + lane);
    int v1 = __ldg(adj + base + 32 + lane);
    int v2 = __ldg(adj + base + 64 + lane);
    int v3 = __ldg(adj + base + 96 + lane);
    uint32_t b0 = __ballot_sync(0xffffffffu, v0 > 0);
    uint32_t b1 = __ballot_sync(0xffffffffu, v1 > 0);
    uint32_t b2 = __ballot_sync(0xffffffffu, v2 > 0);
    uint32_t b3 = __ballot_sync(0xffffffffu, v3 > 0);
    if (lane == 0)
        *(uint4*)&g_adjb[base >> 5] = make_uint4(b0, b1, b2, b3);
}

// ---------------- K1: HMMA h = x @ W + scores + fp16 transpose ----------------
__global__ __launch_bounds__(256, 1) void gemm_hmma(const float* __restrict__ a1,
                                                    const float* __restrict__ a2) {
    extern __shared__ char sm[];
    const uint32_t sm_u = smem_u32(sm);
    const int t    = threadIdx.x;
    const int lane = t & 31, wid = t >> 5;
    const int head = blockIdx.x & 3;
    const int m0   = (blockIdx.x >> 2) << 7;

    auto stageA = [&](int kc) {
        const uint32_t Au = sm_u + ((kc & 1) ? GA1 : GA0);
#pragma unroll
        for (int r = 0; r < 4; ++r) {
            int id  = t + (r << 8);
            int row = id >> 3, u = id & 7;
            cpa16(Au + row * PSG + (u << 4),
                  g_xh + (size_t)(m0 + row) * INF + (kc << 6) + (u << 3));
        }
    };
    auto stageB = [&](int kc) {
        const uint32_t Bu = sm_u + ((kc & 1) ? GB1 : GB0);
#pragma unroll
        for (int r = 0; r < 2; ++r) {
            int id  = t + (r << 8);
            int row = id >> 3, u = id & 7;
            cpa16(Bu + row * PSG + (u << 4),
                  g_wh + (size_t)((head << 6) + row) * INF + (kc << 6) + (u << 3));
        }
    };

    stageA(0); stageB(0);
    asm volatile("cp.async.commit_group;");

    const int g  = lane >> 2;
    const int t2 = (lane & 3) << 1;
    const uint32_t lrow = ((lane >> 3) & 1) * 8 + (lane & 7);
    const uint32_t lcol = (lane >> 4) * 16;

    float acc[8][4];
#pragma unroll
    for (int nb = 0; nb < 8; nb++)
#pragma unroll
        for (int q = 0; q < 4; q++) acc[nb][q] = 0.f;

    for (int kc = 0; kc < 4; ++kc) {
        asm volatile("cp.async.wait_group 0;" ::: "memory");
        __syncthreads();
        if (kc < 3) {
            stageA(kc + 1); stageB(kc + 1);
            asm volatile("cp.async.commit_group;");
        }
        const uint32_t Au = sm_u + ((kc & 1) ? GA1 : GA0);
        const uint32_t Bu = sm_u + ((kc & 1) ? GB1 : GB0);
        const uint32_t a_base  = Au + (wid * 16 + lrow) * PSG + lcol;
        const uint32_t b_base0 = Bu + (lrow +  0) * PSG + lcol;
        const uint32_t b_base1 = Bu + (lrow + 16) * PSG + lcol;
        const uint32_t b_base2 = Bu + (lrow + 32) * PSG + lcol;
        const uint32_t b_base3 = Bu + (lrow + 48) * PSG + lcol;
#pragma unroll
        for (int ks = 0; ks < 4; ++ks) {
            const uint32_t ko = ks * 32;
            uint32_t a0, a1r, a2r, a3, b0, b1, b2, b3;
            ldsm4(a0, a1r, a2r, a3, a_base + ko);
            ldsm4(b0, b1, b2, b3, b_base0 + ko);
            mma16816(acc[0], a0, a1r, a2r, a3, b0, b2);
            mma16816(acc[1], a0, a1r, a2r, a3, b1, b3);
            ldsm4(b0, b1, b2, b3, b_base1 + ko);
            mma16816(acc[2], a0, a1r, a2r, a3, b0, b2);
            mma16816(acc[3], a0, a1r, a2r, a3, b1, b3);
            ldsm4(b0, b1, b2, b3, b_base2 + ko);
            mma16816(acc[4], a0, a1r, a2r, a3, b0, b2);
            mma16816(acc[5], a0, a1r, a2r, a3, b1, b3);
            ldsm4(b0, b1, b2, b3, b_base3 + ko);
            mma16816(acc[6], a0, a1r, a2r, a3, b0, b2);
            mma16816(acc[7], a0, a1r, a2r, a3, b1, b3);
        }
    }

    float s1r0 = 0.f, s1r1 = 0.f, s2r0 = 0.f, s2r1 = 0.f;
#pragma unroll
    for (int nb = 0; nb < 8; ++nb) {
        const int c0 = (nb << 3) + t2;
        float a1a = __ldg(a1 + c0), a1b = __ldg(a1 + c0 + 1);
        float a2a = __ldg(a2 + c0), a2b = __ldg(a2 + c0 + 1);
        s1r0 += acc[nb][0] * a1a + acc[nb][1] * a1b;
        s2r0 += acc[nb][0] * a2a + acc[nb][1] * a2b;
        s1r1 += acc[nb][2] * a1a + acc[nb][3] * a1b;
        s2r1 += acc[nb][2] * a2a + acc[nb][3] * a2b;
    }
#pragma unroll
    for (int m = 1; m < 4; m <<= 1) {
        s1r0 += __shfl_xor_sync(0xffffffffu, s1r0, m);
        s2r0 += __shfl_xor_sync(0xffffffffu, s2r0, m);
        s1r1 += __shfl_xor_sync(0xffffffffu, s1r1, m);
        s2r1 += __shfl_xor_sync(0xffffffffu, s2r1, m);
    }

    __syncthreads();
    __half* Ts = (__half*)(sm);
    float2* sb = (float2*)(sm + GSB);
    if ((lane & 3) == 0) {
        const int r = wid * 16 + g;
        sb[r]     = make_float2(s1r0, s2r0);
        sb[r + 8] = make_float2(s1r1, s2r1);
    }
    {
        const int r = wid * 16 + g;
#pragma unroll
        for (int nb = 0; nb < 8; ++nb) {
            const int c0 = (nb << 3) + t2;
            Ts[c0 * 136 + r]           = __float2half(acc[nb][0]);
            Ts[(c0 + 1) * 136 + r]     = __float2half(acc[nb][1]);
            Ts[c0 * 136 + r + 8]       = __float2half(acc[nb][2]);
            Ts[(c0 + 1) * 136 + r + 8] = __float2half(acc[nb][3]);
        }
    }
    __syncthreads();

    if (t < 128) {
        float2 s = sb[t];
        g_fi[head * NN + m0 + t] =
            make_float4(s.x, __expf(s.x), __expf(0.2f * s.x), 0.f);
    } else if (t < 192) {
        const int p = t - 128;
        float2 sa = sb[2 * p], sbv = sb[2 * p + 1];
        uint4 o;
        o.x = bitsh2(__floats2half2_rn(sa.y, sbv.y));
        o.y = bitsh2(__floats2half2_rn(__expf(sa.y), __expf(sbv.y)));
        o.z = bitsh2(__floats2half2_rn(__expf(0.2f * sa.y), __expf(0.2f * sbv.y)));
        o.w = 0;
        g_fjp[head * (NN / 2) + (m0 >> 1) + p] = o;
    }
#pragma unroll
    for (int r = 0; r < 4; ++r) {
        int id = t + (r << 8);
        int f  = id >> 4, u = id & 15;
        uint4 v = *(const uint4*)(sm + f * PSB + (u << 4));
        *(uint4*)(g_ht + (((size_t)((head << 6) + f)) << 12) + m0 + (u << 3)) = v;
    }
}

// ---------------- K3: dual-warpgroup pipelined HMMA aggregation ----------------
// CTA = (64 i-rows, head), 256 threads / 8 warps. Group 0 -> even j-chunks,
// group 1 -> odd; 4 B buffers; fp32 combine in smem at the end.
__global__ __launch_bounds__(256, 2) void aggregate_mma(float* __restrict__ out) {
    extern __shared__ char sm[];
    const int t    = threadIdx.x;
    const int lane = t & 31, wid = t >> 5;
    const int grp  = wid >> 2;        // warp-group 0/1
    const int wl   = wid & 3;         // warp within group
    const int head = blockIdx.x & 3;
    const int i0   = (blockIdx.x >> 2) << 6;

    const uint32_t sm_u  = smem_u32(sm);
    const uint32_t fjp_u = sm_u + SM_FJP;
    const uint32_t Bb_u  = sm_u + SM_BS;

    const int g   = lane >> 2;
    const int c2q = lane & 3;
    const int t2  = c2q << 1;

    const int rA = i0 + wl * 16 + g;
    const float4 fiA = __ldg(&g_fi[head * NN + rA]);
    const float4 fiB = __ldg(&g_fi[head * NN + rA + 8]);
    const __half2 negA = __float2half2_rn(-fiA.x), epA = __float2half2_rn(fiA.y),
                  enA  = __float2half2_rn(fiA.z);
    const __half2 negB = __float2half2_rn(-fiB.x), epB = __float2half2_rn(fiB.y),
                  enB  = __float2half2_rn(fiB.z);
    const uint32_t* __restrict__ adjA = g_adjb + ((size_t)rA << 7);
    const uint32_t* __restrict__ adjB = g_adjb + ((size_t)(rA + 8) << 7);

    // 256-thread staging: one chunk = 64-row B tile + 64 fjp uint4
    auto stage = [&](int cc) {
        const int j0  = cc << 7;
        const int buf = cc & 3;
        if (t < 64)
            cpa16(fjp_u + buf * 1024 + t * 16,
                  (const char*)(g_fjp + head * (NN / 2) + (j0 >> 1) + t));
#pragma unroll
        for (int r = 0; r < 4; ++r) {
            int id = t + (r << 8);
            int f  = id >> 4, u = id & 15;
            cpa16(Bb_u + buf * BBUF + f * PSB + (u << 4),
                  g_ht + (((size_t)((head << 6) + f)) << 12) + j0 + (u << 3));
        }
    };

    stage(0); stage(1);
    asm volatile("cp.async.commit_group;");

    uint32_t awA[4], awB[4];
    {
        const int o0 = grp << 2;      // my group's first chunk = grp
#pragma unroll
        for (int q = 0; q < 4; ++q) { awA[q] = __ldg(adjA + o0 + q); awB[q] = __ldg(adjB + o0 + q); }
    }

    const uint32_t lrow = ((lane >> 3) & 1) * 8 + (lane & 7);
    const uint32_t lcol = (lane >> 4) * 16;
    const uint32_t zfrag = (lane < 4) ? 0x3C003C00u : 0u;

    float acc[8][4];
    float accz[4];
#pragma unroll
    for (int nb = 0; nb < 8; nb++)
#pragma unroll
        for (int q = 0; q < 4; q++) acc[nb][q] = 0.f;
#pragma unroll
    for (int q = 0; q < 4; q++) accz[q] = 0.f;

    for (int s = 0; s < 16; ++s) {
        asm volatile("cp.async.wait_group 0;" ::: "memory");
        __syncthreads();   // both groups past step s-1 MMA; buffers (2s+2)&3,(2s+3)&3 free
        if (s < 15) {
            stage(2 * s + 2); stage(2 * s + 3);
            asm volatile("cp.async.commit_group;");
        }
        // prefetch my group's next adjacency words (hidden behind MMA)
        uint32_t nxA[4], nxB[4];
        if (s < 15) {
            const int o = ((s + 1) << 3) + (grp << 2);
#pragma unroll
            for (int q = 0; q < 4; ++q) { nxA[q] = __ldg(adjA + o + q); nxB[q] = __ldg(adjB + o + q); }
        }

        const int buf = (2 * s + grp) & 3;
        const uint32_t Bu = Bb_u + buf * BBUF;
        const uint32_t b_base0 = Bu + (lrow +  0) * PSB + lcol;
        const uint32_t b_base1 = Bu + (lrow + 16) * PSB + lcol;
        const uint32_t b_base2 = Bu + (lrow + 32) * PSB + lcol;
        const uint32_t b_base3 = Bu + (lrow + 48) * PSB + lcol;
        const uint32_t fq = fjp_u + buf * 1024 + c2q * 16;

#pragma unroll
        for (int ks = 0; ks < 8; ++ks) {
            uint32_t qax, qay, qaz, qaw, qbx, qby, qbz, qbw;
            asm volatile("ld.shared.v4.b32 {%0,%1,%2,%3}, [%4];"
                         : "=r"(qax), "=r"(qay), "=r"(qaz), "=r"(qaw)
                         : "r"(fq + ks * 128));
            asm volatile("ld.shared.v4.b32 {%0,%1,%2,%3}, [%4];"
                         : "=r"(qbx), "=r"(qby), "=r"(qbz), "=r"(qbw)
                         : "r"(fq + ks * 128 + 64));
            const uint4 qav = make_uint4(qax, qay, qaz, qaw);
            const uint4 qbv = make_uint4(qbx, qby, qbz, qbw);
            const int pos = ((ks & 1) << 4) + t2;
            const uint32_t wA = awA[ks >> 1], wB = awB[ks >> 1];
            uint32_t a0 = wcalc(qav, (wA >> pos) & 3u,       negA, epA, enA);
            uint32_t a1 = wcalc(qav, (wB >> pos) & 3u,       negB, epB, enB);
            uint32_t a2 = wcalc(qbv, (wA >> (pos + 8)) & 3u, negA, epA, enA);
            uint32_t a3 = wcalc(qbv, (wB >> (pos + 8)) & 3u, negB, epB, enB);

            const uint32_t ko = ks * 32;
            uint32_t b0, b1, b2, b3;
            ldsm4(b0, b1, b2, b3, b_base0 + ko);
            mma16816(acc[0], a0, a1, a2, a3, b0, b2);
            mma16816(acc[1], a0, a1, a2, a3, b1, b3);
            ldsm4(b0, b1, b2, b3, b_base1 + ko);
            mma16816(acc[2], a0, a1, a2, a3, b0, b2);
            mma16816(acc[3], a0, a1, a2, a3, b1, b3);
            ldsm4(b0, b1, b2, b3, b_base2 + ko);
            mma16816(acc[4], a0, a1, a2, a3, b0, b2);
            mma16816(acc[5], a0, a1, a2, a3, b1, b3);
            ldsm4(b0, b1, b2, b3, b_base3 + ko);
            mma16816(acc[6], a0, a1, a2, a3, b0, b2);
            mma16816(acc[7], a0, a1, a2, a3, b1, b3);
            mma16816(accz, a0, a1, a2, a3, zfrag, zfrag);
        }
#pragma unroll
        for (int q = 0; q < 4; ++q) { awA[q] = nxA[q]; awB[q] = nxB[q]; }
    }

    // ---- combine the two warp-groups (fp32, in smem; stride 37 = conflict-free) ----
    __syncthreads();
    float* red = (float*)(sm + RED_OFF);
    if (grp == 1) {
        const int base = (t & 127) * 37;
#pragma unroll
        for (int nb = 0; nb < 8; ++nb)
#pragma unroll
            for (int q = 0; q < 4; ++q) red[base + nb * 4 + q] = acc[nb][q];
#pragma unroll
        for (int q = 0; q < 4; ++q) red[base + 32 + q] = accz[q];
    }
    __syncthreads();
    if (grp == 0) {
        const int base = t * 37;
#pragma unroll
        for (int nb = 0; nb < 8; ++nb)
#pragma unroll
            for (int q = 0; q < 4; ++q) acc[nb][q] += red[base + nb * 4 + q];
#pragma unroll
        for (int q = 0; q < 4; ++q) accz[q] += red[base + 32 + q];

        const float z0 = __shfl_sync(0xffffffffu, accz[0], lane & ~3);
        const float z1 = __shfl_sync(0xffffffffu, accz[2], lane & ~3);
        const float rz0 = 1.0f / z0;
        const float rz1 = 1.0f / z1;

        const int r0 = wl * 16 + g;
        float* const ob = out + (size_t)(i0 + r0) * HD + (head << 6) + t2;
#pragma unroll
        for (int nb = 0; nb < 8; ++nb) {
            *(float2*)(ob + nb * 8)          = make_float2(acc[nb][0] * rz0, acc[nb][1] * rz0);
            *(float2*)(ob + nb * 8 + 8 * HD) = make_float2(acc[nb][2] * rz1, acc[nb][3] * rz1);
        }
    }
}

extern "C" void kernel_launch(void* const* d_in, const int* in_sizes, int n_in,
                              void* d_out, int out_size) {
    const float* x   = (const float*)d_in[0];
    const int*   adj = (const int*)  d_in[1];
    const float* W   = (const float*)d_in[2];
    const float* a1  = (const float*)d_in[3];
    const float* a2  = (const float*)d_in[4];
    float* out = (float*)d_out;

    cudaFuncSetAttribute(gemm_hmma,     cudaFuncAttributeMaxDynamicSharedMemorySize, GTOT);
    cudaFuncSetAttribute(aggregate_mma, cudaFuncAttributeMaxDynamicSharedMemorySize, SM_TOT);

    cvt_inputs   <<<1024 + 256, 256>>>(x, W);
    gemm_hmma    <<<(NN / 128) * H, 256, GTOT>>>(a1, a2);
    pack_adj     <<<NN * NN / 128 / 8, 256>>>(adj);
    aggregate_mma<<<(NN / 64) * H, 256, SM_TOT>>>(out);
}

// round 15
// speedup vs baseline: 7.4603x; 1.0260x over previous
#include <cuda_runtime.h>
#include <cuda_fp16.h>
#include <cstdint>

#define NN   4096
#define INF  256
#define HD   256   // H*D
#define H    4
#define D    64

// ---------------- device scratch (no cudaMalloc allowed) ----------------
__device__ float4   g_fi [H * NN];                   // (si, e^si, e^.2si, 0) fp32
__device__ __align__(16) uint4  g_fjp[H * NN / 2];   // per (h, j-pair): {sj2, e^sj2, e^.2sj2, 0}
__device__ __align__(16) __half g_ht [H * D * NN];   // h transposed per head: [h][f][j]
__device__ __align__(16) uint32_t g_adjb[NN * NN / 32];  // packed adjacency bits
__device__ __align__(16) __half g_xh [NN * INF];     // x in fp16
__device__ __align__(16) __half g_wh [HD * INF];     // W^T in fp16: [n][k]

// ---------------- smem layouts ----------------
#define PSB    272                    // aggregate B row stride (136 halfs)
#define BBUF   17408                  // one B buffer: 64 rows x 272
#define SM_FJP 0                      // 4 x uint4[64] = 4096
#define SM_BS  4096                   // 4 x 17408 = 69632
#define SM_TOT 73728
#define RED_OFF 4096                  // combine scratch aliases B buffers post-loop

#define PSG    144                    // gemm tile row stride (72 halfs)
#define GA0    0
#define GA1    18432
#define GB0    36864
#define GB1    46080
#define GSB    55296
#define GTOT   56320

#define GEMM_BLKS ((NN / 128) * H)    // 128
#define PACK_BLKS (NN * NN / 512 / 8) // 4096 (each warp packs 512 ints)

__device__ __forceinline__ uint32_t smem_u32(const void* p) {
    uint32_t a;
    asm("{ .reg .u64 t; cvta.to.shared.u64 t, %1; cvt.u32.u64 %0, t; }"
        : "=r"(a) : "l"(p));
    return a;
}

__device__ __forceinline__ void cpa16(uint32_t dst, const void* src) {
    asm volatile("cp.async.cg.shared.global [%0], [%1], 16;" :: "r"(dst), "l"(src));
}

__device__ __forceinline__ void mma16816(float* c,
                                         uint32_t a0, uint32_t a1, uint32_t a2, uint32_t a3,
                                         uint32_t b0, uint32_t b1) {
    asm volatile(
        "mma.sync.aligned.m16n8k16.row.col.f32.f16.f16.f32 "
        "{%0,%1,%2,%3}, {%4,%5,%6,%7}, {%8,%9}, {%0,%1,%2,%3};"
        : "+f"(c[0]), "+f"(c[1]), "+f"(c[2]), "+f"(c[3])
        : "r"(a0), "r"(a1), "r"(a2), "r"(a3), "r"(b0), "r"(b1));
}

__device__ __forceinline__ void ldsm4(uint32_t& r0, uint32_t& r1, uint32_t& r2, uint32_t& r3,
                                      uint32_t addr) {
    asm volatile("ldmatrix.sync.aligned.m8n8.x4.shared.b16 {%0,%1,%2,%3}, [%4];"
                 : "=r"(r0), "=r"(r1), "=r"(r2), "=r"(r3) : "r"(addr));
}

__device__ __forceinline__ __half2 h2bits(uint32_t v) { return *(__half2*)&v; }
__device__ __forceinline__ uint32_t bitsh2(__half2 v) { return *(uint32_t*)&v; }

__device__ __forceinline__ uint32_t wcalc(uint4 q, uint32_t bb,
                                          __half2 negsi2, __half2 epi2, __half2 eni2) {
    __half2 cond = __hgt2(h2bits(q.x), negsi2);
    __half2 ph   = __hmul2(epi2, h2bits(q.y));
    __half2 pl   = __hmul2(eni2, h2bits(q.z));
    __half2 w    = __hfma2(cond, __hsub2(ph, pl), pl);
    uint32_t mb  = (bb & 1u) * 0x3C00u + (bb & 2u) * 0x1E000000u;
    return bitsh2(__hmul2(w, h2bits(mb)));
}

// ---------------- K_cvt: fp16 copies of x and W^T ----------------
__global__ __launch_bounds__(256) void cvt_inputs(const float* __restrict__ x,
                                                  const float* __restrict__ W) {
    const int b = blockIdx.x, t = threadIdx.x;
    if (b < 1024) {
        int id = (b << 8) + t;
        float4 v = *(const float4*)(x + (size_t)id * 4);
        uint2 o;
        o.x = bitsh2(__floats2half2_rn(v.x, v.y));
        o.y = bitsh2(__floats2half2_rn(v.z, v.w));
        *(uint2*)(g_xh + (size_t)id * 4) = o;
    } else {
        int id = ((b - 1024) << 8) + t;
        int n = id >> 8, k = id & 255;
        g_wh[(size_t)n * INF + k] = __float2half(__ldg(W + (size_t)k * HD + n));
    }
}

// ---------------- K1: merged HMMA gemm (+scores, +fp16 transpose) AND adj pack ----------------
// blocks [0, GEMM_BLKS): gemm; blocks [GEMM_BLKS, +PACK_BLKS): ballot-pack adjacency.
__global__ __launch_bounds__(256, 1) void gemm_pack(const float* __restrict__ a1,
                                                    const float* __restrict__ a2,
                                                    const int* __restrict__ adj) {
    const int t = threadIdx.x;
    if (blockIdx.x >= GEMM_BLKS) {
        // ---- adjacency pack: warp packs 512 ints with 16 loads in flight ----
        const int wg   = (blockIdx.x - GEMM_BLKS) * 8 + (t >> 5);
        const int lane = t & 31;
        const size_t base = (size_t)wg << 9;          // 512 ints
        uint32_t bits[16];
#pragma unroll
        for (int r = 0; r < 16; ++r) {
            int v = __ldg(adj + base + (r << 5) + lane);
            bits[r] = __ballot_sync(0xffffffffu, v > 0);
        }
        if (lane == 0) {
#pragma unroll
            for (int r = 0; r < 4; ++r)
                *(uint4*)&g_adjb[(base >> 5) + (r << 2)] =
                    make_uint4(bits[4 * r], bits[4 * r + 1],
                               bits[4 * r + 2], bits[4 * r + 3]);
        }
        return;
    }

    extern __shared__ char sm[];
    const uint32_t sm_u = smem_u32(sm);
    const int lane = t & 31, wid = t >> 5;
    const int head = blockIdx.x & 3;
    const int m0   = (blockIdx.x >> 2) << 7;

    auto stageA = [&](int kc) {
        const uint32_t Au = sm_u + ((kc & 1) ? GA1 : GA0);
#pragma unroll
        for (int r = 0; r < 4; ++r) {
            int id  = t + (r << 8);
            int row = id >> 3, u = id & 7;
            cpa16(Au + row * PSG + (u << 4),
                  g_xh + (size_t)(m0 + row) * INF + (kc << 6) + (u << 3));
        }
    };
    auto stageB = [&](int kc) {
        const uint32_t Bu = sm_u + ((kc & 1) ? GB1 : GB0);
#pragma unroll
        for (int r = 0; r < 2; ++r) {
            int id  = t + (r << 8);
            int row = id >> 3, u = id & 7;
            cpa16(Bu + row * PSG + (u << 4),
                  g_wh + (size_t)((head << 6) + row) * INF + (kc << 6) + (u << 3));
        }
    };

    stageA(0); stageB(0);
    asm volatile("cp.async.commit_group;");

    const int g  = lane >> 2;
    const int t2 = (lane & 3) << 1;
    const uint32_t lrow = ((lane >> 3) & 1) * 8 + (lane & 7);
    const uint32_t lcol = (lane >> 4) * 16;

    float acc[8][4];
#pragma unroll
    for (int nb = 0; nb < 8; nb++)
#pragma unroll
        for (int q = 0; q < 4; q++) acc[nb][q] = 0.f;

    for (int kc = 0; kc < 4; ++kc) {
        asm volatile("cp.async.wait_group 0;" ::: "memory");
        __syncthreads();
        if (kc < 3) {
            stageA(kc + 1); stageB(kc + 1);
            asm volatile("cp.async.commit_group;");
        }
        const uint32_t Au = sm_u + ((kc & 1) ? GA1 : GA0);
        const uint32_t Bu = sm_u + ((kc & 1) ? GB1 : GB0);
        const uint32_t a_base  = Au + (wid * 16 + lrow) * PSG + lcol;
        const uint32_t b_base0 = Bu + (lrow +  0) * PSG + lcol;
        const uint32_t b_base1 = Bu + (lrow + 16) * PSG + lcol;
        const uint32_t b_base2 = Bu + (lrow + 32) * PSG + lcol;
        const uint32_t b_base3 = Bu + (lrow + 48) * PSG + lcol;
#pragma unroll
        for (int ks = 0; ks < 4; ++ks) {
            const uint32_t ko = ks * 32;
            uint32_t a0, a1r, a2r, a3;
            uint32_t p0[4], p1[4];
            ldsm4(a0, a1r, a2r, a3, a_base + ko);
            ldsm4(p0[0], p0[1], p0[2], p0[3], b_base0 + ko);
            ldsm4(p1[0], p1[1], p1[2], p1[3], b_base1 + ko);
            mma16816(acc[0], a0, a1r, a2r, a3, p0[0], p0[2]);
            mma16816(acc[1], a0, a1r, a2r, a3, p0[1], p0[3]);
            ldsm4(p0[0], p0[1], p0[2], p0[3], b_base2 + ko);
            mma16816(acc[2], a0, a1r, a2r, a3, p1[0], p1[2]);
            mma16816(acc[3], a0, a1r, a2r, a3, p1[1], p1[3]);
            ldsm4(p1[0], p1[1], p1[2], p1[3], b_base3 + ko);
            mma16816(acc[4], a0, a1r, a2r, a3, p0[0], p0[2]);
            mma16816(acc[5], a0, a1r, a2r, a3, p0[1], p0[3]);
            mma16816(acc[6], a0, a1r, a2r, a3, p1[0], p1[2]);
            mma16816(acc[7], a0, a1r, a2r, a3, p1[1], p1[3]);
        }
    }

    float s1r0 = 0.f, s1r1 = 0.f, s2r0 = 0.f, s2r1 = 0.f;
#pragma unroll
    for (int nb = 0; nb < 8; ++nb) {
        const int c0 = (nb << 3) + t2;
        float a1a = __ldg(a1 + c0), a1b = __ldg(a1 + c0 + 1);
        float a2a = __ldg(a2 + c0), a2b = __ldg(a2 + c0 + 1);
        s1r0 += acc[nb][0] * a1a + acc[nb][1] * a1b;
        s2r0 += acc[nb][0] * a2a + acc[nb][1] * a2b;
        s1r1 += acc[nb][2] * a1a + acc[nb][3] * a1b;
        s2r1 += acc[nb][2] * a2a + acc[nb][3] * a2b;
    }
#pragma unroll
    for (int m = 1; m < 4; m <<= 1) {
        s1r0 += __shfl_xor_sync(0xffffffffu, s1r0, m);
        s2r0 += __shfl_xor_sync(0xffffffffu, s2r0, m);
        s1r1 += __shfl_xor_sync(0xffffffffu, s1r1, m);
        s2r1 += __shfl_xor_sync(0xffffffffu, s2r1, m);
    }

    __syncthreads();
    __half* Ts = (__half*)(sm);
    float2* sb = (float2*)(sm + GSB);
    if ((lane & 3) == 0) {
        const int r = wid * 16 + g;
        sb[r]     = make_float2(s1r0, s2r0);
        sb[r + 8] = make_float2(s1r1, s2r1);
    }
    {
        const int r = wid * 16 + g;
#pragma unroll
        for (int nb = 0; nb < 8; ++nb) {
            const int c0 = (nb << 3) + t2;
            Ts[c0 * 136 + r]           = __float2half(acc[nb][0]);
            Ts[(c0 + 1) * 136 + r]     = __float2half(acc[nb][1]);
            Ts[c0 * 136 + r + 8]       = __float2half(acc[nb][2]);
            Ts[(c0 + 1) * 136 + r + 8] = __float2half(acc[nb][3]);
        }
    }
    __syncthreads();

    if (t < 128) {
        float2 s = sb[t];
        g_fi[head * NN + m0 + t] =
            make_float4(s.x, __expf(s.x), __expf(0.2f * s.x), 0.f);
    } else if (t < 192) {
        const int p = t - 128;
        float2 sa = sb[2 * p], sbv = sb[2 * p + 1];
        uint4 o;
        o.x = bitsh2(__floats2half2_rn(sa.y, sbv.y));
        o.y = bitsh2(__floats2half2_rn(__expf(sa.y), __expf(sbv.y)));
        o.z = bitsh2(__floats2half2_rn(__expf(0.2f * sa.y), __expf(0.2f * sbv.y)));
        o.w = 0;
        g_fjp[head * (NN / 2) + (m0 >> 1) + p] = o;
    }
#pragma unroll
    for (int r = 0; r < 4; ++r) {
        int id = t + (r << 8);
        int f  = id >> 4, u = id & 15;
        uint4 v = *(const uint4*)(sm + f * PSB + (u << 4));
        *(uint4*)(g_ht + (((size_t)((head << 6) + f)) << 12) + m0 + (u << 3)) = v;
    }
}

// ---------------- K3: dual-warpgroup pipelined HMMA aggregation ----------------
// CTA = (64 i-rows, head), 256 threads / 8 warps. Group 0 -> even j-chunks,
// group 1 -> odd; 4 B buffers; ldsm/mma software-pipelined; fp32 combine at end.
__global__ __launch_bounds__(256, 2) void aggregate_mma(float* __restrict__ out) {
    extern __shared__ char sm[];
    const int t    = threadIdx.x;
    const int lane = t & 31, wid = t >> 5;
    const int grp  = wid >> 2;
    const int wl   = wid & 3;
    const int head = blockIdx.x & 3;
    const int i0   = (blockIdx.x >> 2) << 6;

    const uint32_t sm_u  = smem_u32(sm);
    const uint32_t fjp_u = sm_u + SM_FJP;
    const uint32_t Bb_u  = sm_u + SM_BS;

    const int g   = lane >> 2;
    const int c2q = lane & 3;
    const int t2  = c2q << 1;

    const int rA = i0 + wl * 16 + g;
    const float4 fiA = __ldg(&g_fi[head * NN + rA]);
    const float4 fiB = __ldg(&g_fi[head * NN + rA + 8]);
    const __half2 negA = __float2half2_rn(-fiA.x), epA = __float2half2_rn(fiA.y),
                  enA  = __float2half2_rn(fiA.z);
    const __half2 negB = __float2half2_rn(-fiB.x), epB = __float2half2_rn(fiB.y),
                  enB  = __float2half2_rn(fiB.z);
    const uint32_t* __restrict__ adjA = g_adjb + ((size_t)rA << 7);
    const uint32_t* __restrict__ adjB = g_adjb + ((size_t)(rA + 8) << 7);

    auto stage = [&](int cc) {
        const int j0  = cc << 7;
        const int buf = cc & 3;
        if (t < 64)
            cpa16(fjp_u + buf * 1024 + t * 16,
                  (const char*)(g_fjp + head * (NN / 2) + (j0 >> 1) + t));
#pragma unroll
        for (int r = 0; r < 4; ++r) {
            int id = t + (r << 8);
            int f  = id >> 4, u = id & 15;
            cpa16(Bb_u + buf * BBUF + f * PSB + (u << 4),
                  g_ht + (((size_t)((head << 6) + f)) << 12) + j0 + (u << 3));
        }
    };

    stage(0); stage(1);
    asm volatile("cp.async.commit_group;");

    uint32_t awA[4], awB[4];
    {
        const int o0 = grp << 2;
#pragma unroll
        for (int q = 0; q < 4; ++q) { awA[q] = __ldg(adjA + o0 + q); awB[q] = __ldg(adjB + o0 + q); }
    }

    const uint32_t lrow = ((lane >> 3) & 1) * 8 + (lane & 7);
    const uint32_t lcol = (lane >> 4) * 16;
    const uint32_t zfrag = (lane < 4) ? 0x3C003C00u : 0u;

    float acc[8][4];
    float accz[4];
#pragma unroll
    for (int nb = 0; nb < 8; nb++)
#pragma unroll
        for (int q = 0; q < 4; q++) acc[nb][q] = 0.f;
#pragma unroll
    for (int q = 0; q < 4; q++) accz[q] = 0.f;

    for (int s = 0; s < 16; ++s) {
        asm volatile("cp.async.wait_group 0;" ::: "memory");
        __syncthreads();
        if (s < 15) {
            stage(2 * s + 2); stage(2 * s + 3);
            asm volatile("cp.async.commit_group;");
        }
        uint32_t nxA[4], nxB[4];
        if (s < 15) {
            const int o = ((s + 1) << 3) + (grp << 2);
#pragma unroll
            for (int q = 0; q < 4; ++q) { nxA[q] = __ldg(adjA + o + q); nxB[q] = __ldg(adjB + o + q); }
        }

        const int buf = (2 * s + grp) & 3;
        const uint32_t Bu = Bb_u + buf * BBUF;
        const uint32_t b_base0 = Bu + (lrow +  0) * PSB + lcol;
        const uint32_t b_base1 = Bu + (lrow + 16) * PSB + lcol;
        const uint32_t b_base2 = Bu + (lrow + 32) * PSB + lcol;
        const uint32_t b_base3 = Bu + (lrow + 48) * PSB + lcol;
        const uint32_t fq = fjp_u + buf * 1024 + c2q * 16;

#pragma unroll
        for (int ks = 0; ks < 8; ++ks) {
            const uint32_t ko = ks * 32;
            uint32_t p0[4], p1[4];
            // issue first two B loads; weight-gen ALU below fills their latency
            ldsm4(p0[0], p0[1], p0[2], p0[3], b_base0 + ko);
            ldsm4(p1[0], p1[1], p1[2], p1[3], b_base1 + ko);

            uint32_t qax, qay, qaz, qaw, qbx, qby, qbz, qbw;
            asm volatile("ld.shared.v4.b32 {%0,%1,%2,%3}, [%4];"
                         : "=r"(qax), "=r"(qay), "=r"(qaz), "=r"(qaw)
                         : "r"(fq + ks * 128));
            asm volatile("ld.shared.v4.b32 {%0,%1,%2,%3}, [%4];"
                         : "=r"(qbx), "=r"(qby), "=r"(qbz), "=r"(qbw)
                         : "r"(fq + ks * 128 + 64));
            const uint4 qav = make_uint4(qax, qay, qaz, qaw);
            const uint4 qbv = make_uint4(qbx, qby, qbz, qbw);
            const int pos = ((ks & 1) << 4) + t2;
            const uint32_t wA = awA[ks >> 1], wB = awB[ks >> 1];
            uint32_t a0 = wcalc(qav, (wA >> pos) & 3u,       negA, epA, enA);
            uint32_t a1 = wcalc(qav, (wB >> pos) & 3u,       negB, epB, enB);
            uint32_t a2 = wcalc(qbv, (wA >> (pos + 8)) & 3u, negA, epA, enA);
            uint32_t a3 = wcalc(qbv, (wB >> (pos + 8)) & 3u, negB, epB, enB);

            mma16816(acc[0], a0, a1, a2, a3, p0[0], p0[2]);
            mma16816(acc[1], a0, a1, a2, a3, p0[1], p0[3]);
            ldsm4(p0[0], p0[1], p0[2], p0[3], b_base2 + ko);
            mma16816(acc[2], a0, a1, a2, a3, p1[0], p1[2]);
            mma16816(acc[3], a0, a1, a2, a3, p1[1], p1[3]);
            ldsm4(p1[0], p1[1], p1[2], p1[3], b_base3 + ko);
            mma16816(accz, a0, a1, a2, a3, zfrag, zfrag);   // fills ldsm shadow
            mma16816(acc[4], a0, a1, a2, a3, p0[0], p0[2]);
            mma16816(acc[5], a0, a1, a2, a3, p0[1], p0[3]);
            mma16816(acc[6], a0, a1, a2, a3, p1[0], p1[2]);
            mma16816(acc[7], a0, a1, a2, a3, p1[1], p1[3]);
        }
#pragma unroll
        for (int q = 0; q < 4; ++q) { awA[q] = nxA[q]; awB[q] = nxB[q]; }
    }

    // ---- combine the two warp-groups (fp32, in smem; stride 37 = conflict-free) ----
    __syncthreads();
    float* red = (float*)(sm + RED_OFF);
    if (grp == 1) {
        const int base = (t & 127) * 37;
#pragma unroll
        for (int nb = 0; nb < 8; ++nb)
#pragma unroll
            for (int q = 0; q < 4; ++q) red[base + nb * 4 + q] = acc[nb][q];
#pragma unroll
        for (int q = 0; q < 4; ++q) red[base + 32 + q] = accz[q];
    }
    __syncthreads();
    if (grp == 0) {
        const int base = t * 37;
#pragma unroll
        for (int nb = 0; nb < 8; ++nb)
#pragma unroll
            for (int q = 0; q < 4; ++q) acc[nb][q] += red[base + nb * 4 + q];
#pragma unroll
        for (int q = 0; q < 4; ++q) accz[q] += red[base + 32 + q];

        const float z0 = __shfl_sync(0xffffffffu, accz[0], lane & ~3);
        const float z1 = __shfl_sync(0xffffffffu, accz[2], lane & ~3);
        const float rz0 = 1.0f / z0;
        const float rz1 = 1.0f / z1;

        const int r0 = wl * 16 + g;
        float* const ob = out + (size_t)(i0 + r0) * HD + (head << 6) + t2;
#pragma unroll
        for (int nb = 0; nb < 8; ++nb) {
            *(float2*)(ob + nb * 8)          = make_float2(acc[nb][0] * rz0, acc[nb][1] * rz0);
            *(float2*)(ob + nb * 8 + 8 * HD) = make_float2(acc[nb][2] * rz1, acc[nb][3] * rz1);
        }
    }
}

extern "C" void kernel_launch(void* const* d_in, const int* in_sizes, int n_in,
                              void* d_out, int out_size) {
    const float* x   = (const float*)d_in[0];
    const int*   adj = (const int*)  d_in[1];
    const float* W   = (const float*)d_in[2];
    const float* a1  = (const float*)d_in[3];
    const float* a2  = (const float*)d_in[4];
    float* out = (float*)d_out;

    cudaFuncSetAttribute(gemm_pack,     cudaFuncAttributeMaxDynamicSharedMemorySize, GTOT);
    cudaFuncSetAttribute(aggregate_mma, cudaFuncAttributeMaxDynamicSharedMemorySize, SM_TOT);

    cvt_inputs   <<<1024 + 256, 256>>>(x, W);
    gemm_pack    <<<GEMM_BLKS + PACK_BLKS, 256, GTOT>>>(a1, a2, adj);
    aggregate_mma<<<(NN / 64) * H, 256, SM_TOT>>>(out);
}